// round 10
// baseline (speedup 1.0000x reference)
#include <cuda_runtime.h>
#include <cstdint>

#define N_NODES 10000
#define N_EDGES 320000

// ---------------- scratch (device globals; allocation-free) ----------------
__device__ float g_h[N_NODES * 64];                 // 2.56 MB
__device__ float g_agg[(size_t)N_NODES * 576];      // 23 MB; zeroed by k_down after read
__device__ int   g_count[N_NODES];                  // zeroed by k_scan after read
__device__ int   g_rowstart[N_NODES + 1];
__device__ int   g_cursor[N_NODES];
__device__ int   g_csr[N_EDGES];
__device__ int   g_send[N_EDGES];
__device__ int   g_recv[N_EDGES];
__device__ uint4 g_wfrag[5248];                     // fragment-ordered tf32 weights (84KB)

// uint4 offsets into g_wfrag
#define U_W1 0
#define U_W2 128
#define U_W3 1152
#define U_W4 2176       // + chunk*1024

__device__ __forceinline__ float silu_f(float x) {
    return __fdividef(x, 1.f + __expf(-x));
}

__device__ __forceinline__ uint32_t f2tf32(float f) {
    uint32_t r;
    asm("cvt.rna.tf32.f32 %0, %1;" : "=r"(r) : "f"(f));
    return r;
}

__device__ __forceinline__ void mma_tf32(float acc[4], uint32_t a0, uint32_t a1,
                                         uint32_t a2, uint32_t a3,
                                         uint32_t b0, uint32_t b1) {
    asm volatile(
        "mma.sync.aligned.m16n8k8.row.col.f32.tf32.tf32.f32 "
        "{%0,%1,%2,%3}, {%4,%5,%6,%7}, {%8,%9}, {%0,%1,%2,%3};\n"
        : "+f"(acc[0]), "+f"(acc[1]), "+f"(acc[2]), "+f"(acc[3])
        : "r"(a0), "r"(a1), "r"(a2), "r"(a3), "r"(b0), "r"(b1));
}

// fire-and-forget vector float2 reduction (sm_90+)
__device__ __forceinline__ void red2(float* p, float x, float y) {
    asm volatile("red.global.add.v2.f32 [%0], {%1, %2};"
                 :: "l"(p), "f"(x), "f"(y) : "memory");
}

// ---------------- launch 1: count histogram + h GEMM + (blocks>=1250) weight prep ----------------
__global__ __launch_bounds__(256) void k_count_h(const int* __restrict__ recv,
                                                 const float* __restrict__ nf,
                                                 const float* __restrict__ Wup,
                                                 const float* __restrict__ W1,
                                                 const float* __restrict__ W2,
                                                 const float* __restrict__ W3,
                                                 const float* __restrict__ W4) {
    int t = threadIdx.x;
    if (blockIdx.x >= 1250) {
        // weight prep: uint4 { tf32 W[k0][n0], W[k0+4][n0], W[k0][n1], W[k0+4][n1] }
        int u = (blockIdx.x - 1250) * 256 + t;
        if (u >= 5248) return;
        const float* src; int rs, co, KK, local;
        if (u < 128)       { src = W1; rs = 64;  co = 0;   KK = 1; local = u; }
        else if (u < 1152) { src = W2; rs = 64;  co = 0;   KK = 8; local = u - 128; }
        else if (u < 2176) { src = W3; rs = 64;  co = 0;   KK = 8; local = u - 1152; }
        else if (u < 3200) { src = W4; rs = 192; co = 0;   KK = 8; local = u - 2176; }
        else if (u < 4224) { src = W4; rs = 192; co = 64;  KK = 8; local = u - 3200; }
        else               { src = W4; rs = 192; co = 128; KK = 8; local = u - 4224; }
        int lane = local & 31; int rest = local >> 5;
        int np = rest & 1; rest >>= 1;
        int kk = rest % KK; int hb = rest / KK;
        int n0 = co + hb * 32 + np * 16 + (lane >> 2);
        int n1 = n0 + 8;
        int k0 = kk * 8 + (lane & 3);
        g_wfrag[u] = make_uint4(f2tf32(src[(size_t)k0 * rs + n0]),
                                f2tf32(src[(size_t)(k0 + 4) * rs + n0]),
                                f2tf32(src[(size_t)k0 * rs + n1]),
                                f2tf32(src[(size_t)(k0 + 4) * rs + n1]));
        return;
    }

    __shared__ float sW[64 * 64];
    __shared__ float sN[8 * 64];
    int e = blockIdx.x * 256 + t;
    atomicAdd(&g_count[recv[e]], 1);          // N_EDGES % 256 == 0

    for (int idx = t; idx < 1024; idx += 256)
        ((float4*)sW)[idx] = ((const float4*)Wup)[idx];
    int n0 = blockIdx.x * 8;                  // 1250 * 8 = 10000
    if (t < 128)
        ((float4*)sN)[t] = ((const float4*)(nf + (size_t)n0 * 64))[t];
    __syncthreads();

#pragma unroll
    for (int j = 0; j < 2; ++j) {
        int o = t + j * 256;
        int row = o >> 6, c = o & 63;
        float a0 = 0.f, a1 = 0.f;
#pragma unroll
        for (int k = 0; k < 64; k += 2) {
            a0 = fmaf(sN[row * 64 + k],     sW[k * 64 + c],       a0);
            a1 = fmaf(sN[row * 64 + k + 1], sW[(k + 1) * 64 + c], a1);
        }
        g_h[(size_t)(n0 + row) * 64 + c] = (a0 + a1) * 0.125f;
    }
}

// ---------------- launch 2: parallel exclusive scan (+ zero g_count) ----------------
__global__ __launch_bounds__(1024) void k_scan() {
    __shared__ int warpsum[32];
    int t = threadIdx.x, lane = t & 31, w = t >> 5;
    int base = t * 10;
    int c[10];
    int s = 0;
#pragma unroll
    for (int i = 0; i < 10; ++i) {
        int idx = base + i;
        c[i] = (idx < N_NODES) ? g_count[idx] : 0;
        s += c[i];
    }
    int pre = s;
#pragma unroll
    for (int d = 1; d < 32; d <<= 1) {
        int v = __shfl_up_sync(0xffffffffu, pre, d);
        if (lane >= d) pre += v;
    }
    if (lane == 31) warpsum[w] = pre;
    __syncthreads();
    if (w == 0) {
        int v = warpsum[lane];
#pragma unroll
        for (int d = 1; d < 32; d <<= 1) {
            int u = __shfl_up_sync(0xffffffffu, v, d);
            if (lane >= d) v += u;
        }
        warpsum[lane] = v;
    }
    __syncthreads();
    int wbase = (w > 0) ? warpsum[w - 1] : 0;
    int run = wbase + pre - s;
#pragma unroll
    for (int i = 0; i < 10; ++i) {
        int idx = base + i;
        if (idx < N_NODES) {
            g_rowstart[idx] = run;
            g_cursor[idx] = run;
            run += c[i];
            g_count[idx] = 0;
        }
    }
    if (t == 1023) g_rowstart[N_NODES] = warpsum[31];
}

// ---------------- launch 3: CSR fill ----------------
__global__ void k_fill(const int* __restrict__ recv, const int* __restrict__ send) {
    int e = blockIdx.x * blockDim.x + threadIdx.x;
    if (e < N_EDGES) {
        int r = recv[e];
        int pos = atomicAdd(&g_cursor[r], 1);
        g_csr[pos] = e;
        g_send[pos] = send[e];
        g_recv[pos] = r;
    }
}

// ---------------- launch 4 (profiled): warp-autonomous fused MLP + SH + TP + scatter ----------------
// Each warp owns 32 consecutive CSR positions (two 16-row MMA tiles), carrying
// segment accumulators across the tile boundary; flushes use v2 reductions.

__device__ __forceinline__ void layer64(int base, const uint32_t A0[8],
                                        const uint32_t A1[8], const uint32_t A2[8],
                                        const uint32_t A3[8], float acc[8][4],
                                        int lane) {
#pragma unroll
    for (int j = 0; j < 8; ++j) {
        acc[j][0] = 0.f; acc[j][1] = 0.f; acc[j][2] = 0.f; acc[j][3] = 0.f;
    }
#pragma unroll
    for (int kk = 0; kk < 8; ++kk) {
#pragma unroll
        for (int hb = 0; hb < 2; ++hb) {
#pragma unroll
            for (int np = 0; np < 2; ++np) {
                uint4 b = __ldg(&g_wfrag[base + (((hb * 8 + kk) * 2 + np) * 32) + lane]);
                int j = hb * 4 + np * 2;
                mma_tf32(acc[j],     A0[kk], A1[kk], A2[kk], A3[kk], b.x, b.y);
                mma_tf32(acc[j + 1], A0[kk], A1[kk], A2[kk], A3[kk], b.z, b.w);
            }
        }
    }
}

// C-frag -> next layer A-frag conversion (scale + silu + tf32), via shuffles.
__device__ __forceinline__ void cvt_frag(const float acc[8][4], float scale,
                                         uint32_t A0[8], uint32_t A1[8],
                                         uint32_t A2[8], uint32_t A3[8],
                                         int lane, int tid4) {
    int src  = (lane & 28) | (tid4 >> 1);
    int src2 = src + 2;
    bool odd = (tid4 & 1);
#pragma unroll
    for (int j = 0; j < 8; ++j) {
        uint32_t c0 = f2tf32(silu_f(acc[j][0] * scale));
        uint32_t c1 = f2tf32(silu_f(acc[j][1] * scale));
        uint32_t c2 = f2tf32(silu_f(acc[j][2] * scale));
        uint32_t c3 = f2tf32(silu_f(acc[j][3] * scale));
        uint32_t s0 = __shfl_sync(0xffffffffu, c0, src);
        uint32_t s1 = __shfl_sync(0xffffffffu, c1, src);
        uint32_t s2 = __shfl_sync(0xffffffffu, c2, src);
        uint32_t s3 = __shfl_sync(0xffffffffu, c3, src);
        uint32_t u0 = __shfl_sync(0xffffffffu, c0, src2);
        uint32_t u1 = __shfl_sync(0xffffffffu, c1, src2);
        uint32_t u2 = __shfl_sync(0xffffffffu, c2, src2);
        uint32_t u3 = __shfl_sync(0xffffffffu, c3, src2);
        A0[j] = odd ? s1 : s0;
        A1[j] = odd ? s3 : s2;
        A2[j] = odd ? u1 : u0;
        A3[j] = odd ? u3 : u2;
    }
}

template <int D, int KOFF>
__device__ __forceinline__ void l4_chunk(int base, const uint32_t A0[8],
                                         const uint32_t A1[8], const uint32_t A2[8],
                                         const uint32_t A3[8],
                                         int s0r, int s1r,
                                         float* __restrict__ wMsg,
                                         const float* __restrict__ wSh,
                                         const int* __restrict__ wRecv,
                                         int lane, int gid, int tid4,
                                         int ncur_in, float (&car)[D][2], bool last) {
    float acc[8][4];
    layer64(base, A0, A1, A2, A3, acc, lane);

    const float S = 1.f / 256.f;   // 1/sqrt(64) / avg_neigh
#pragma unroll
    for (int j = 0; j < 8; ++j) {
        int col = j * 8 + 2 * tid4;
        float2 h0 = *(const float2*)(g_h + (size_t)s0r * 64 + col);
        float2 h1 = *(const float2*)(g_h + (size_t)s1r * 64 + col);
        *(float2*)(wMsg + gid * 66 + col) =
            make_float2(acc[j][0] * h0.x * S, acc[j][1] * h0.y * S);
        *(float2*)(wMsg + (gid + 8) * 66 + col) =
            make_float2(acc[j][2] * h1.x * S, acc[j][3] * h1.y * S);
    }
    __syncwarp();

    // segment reduction with cross-tile carry: lane owns channels (2l, 2l+1)
    {
        int cn = ncur_in;
#pragma unroll 4
        for (int r = 0; r < 16; ++r) {
            int n = wRecv[r];
            if (n != cn) {
#pragma unroll
                for (int k = 0; k < D; ++k) {
                    red2(&g_agg[(size_t)(cn * 9 + KOFF + k) * 64 + 2 * lane],
                         car[k][0], car[k][1]);
                    car[k][0] = 0.f; car[k][1] = 0.f;
                }
                cn = n;
            }
            float2 m = *(const float2*)(wMsg + r * 66 + 2 * lane);
#pragma unroll
            for (int k = 0; k < D; ++k) {
                float s = wSh[r * 12 + KOFF + k];
                car[k][0] = fmaf(m.x, s, car[k][0]);
                car[k][1] = fmaf(m.y, s, car[k][1]);
            }
        }
        if (last) {
#pragma unroll
            for (int k = 0; k < D; ++k)
                red2(&g_agg[(size_t)(cn * 9 + KOFF + k) * 64 + 2 * lane],
                     car[k][0], car[k][1]);
        }
    }
    __syncwarp();
}

__global__ __launch_bounds__(256, 2) void k_edge(const float* __restrict__ evec,
                                                 const float* __restrict__ rad) {
    __shared__ __align__(16) float sMsgAll[8][16 * 66];   // 33792 B
    __shared__ __align__(16) float sShAll[8][16 * 12];    // 6144 B
    __shared__ int sMeta[8][32];                          // 1024 B

    int t = threadIdx.x, lane = t & 31, warp = t >> 5;
    int gid = lane >> 2, tid4 = lane & 3;
    float* wMsg = sMsgAll[warp];
    float* wSh  = sShAll[warp];
    int* wRecv  = sMeta[warp];
    int* wSend  = sMeta[warp] + 16;
    int wbase = (blockIdx.x * 8 + warp) * 32;

    float car0[1][2] = {{0.f, 0.f}};
    float car1[3][2] = {};
    float car2[5][2] = {};
    int ncur = g_recv[wbase];

#pragma unroll 1
    for (int tile = 0; tile < 2; ++tile) {
        int pos0 = wbase + tile * 16;

        // init: lanes 0..15 handle one row each (SH + meta)
        if (lane < 16) {
            int pos = pos0 + lane;
            int e = g_csr[pos];
            wRecv[lane] = g_recv[pos];
            wSend[lane] = g_send[pos];
            float x = evec[(size_t)e * 3], y = evec[(size_t)e * 3 + 1],
                  z = evec[(size_t)e * 3 + 2];
            float rn = rsqrtf(x * x + y * y + z * z);
            x *= rn; y *= rn; z *= rn;
            const float c3  = 1.7320508075688772f;
            const float c15 = 3.872983346207417f;
            const float c5h = 1.118033988749895f;
            const float c15h= 1.9364916731037085f;
            float* o = wSh + lane * 12;
            o[0] = 1.f;
            o[1] = c3 * x; o[2] = c3 * y; o[3] = c3 * z;
            o[4] = c15 * x * y; o[5] = c15 * y * z;
            o[6] = c5h * (3.f * z * z - 1.f);
            o[7] = c15 * x * z; o[8] = c15h * (x * x - y * y);
        }
        __syncwarp();

        // L1 A-fragments straight from rad (rows gid, gid+8; cols tid4, tid4+4)
        int e0 = g_csr[pos0 + gid], e1 = g_csr[pos0 + gid + 8];
        uint32_t r0 = f2tf32(__ldg(rad + (size_t)e0 * 8 + tid4));
        uint32_t r1 = f2tf32(__ldg(rad + (size_t)e1 * 8 + tid4));
        uint32_t r2 = f2tf32(__ldg(rad + (size_t)e0 * 8 + tid4 + 4));
        uint32_t r3 = f2tf32(__ldg(rad + (size_t)e1 * 8 + tid4 + 4));

        float acc[8][4];
        uint32_t A0[8], A1[8], A2[8], A3[8];

        // L1: [16,8]@[8,64] — 4 uint4 weight loads
#pragma unroll
        for (int j = 0; j < 8; ++j) {
            acc[j][0] = 0.f; acc[j][1] = 0.f; acc[j][2] = 0.f; acc[j][3] = 0.f;
        }
#pragma unroll
        for (int hb = 0; hb < 2; ++hb)
#pragma unroll
            for (int np = 0; np < 2; ++np) {
                uint4 b = __ldg(&g_wfrag[U_W1 + ((hb * 2 + np) * 32) + lane]);
                int j = hb * 4 + np * 2;
                mma_tf32(acc[j],     r0, r1, r2, r3, b.x, b.y);
                mma_tf32(acc[j + 1], r0, r1, r2, r3, b.z, b.w);
            }
        cvt_frag(acc, 0.35355339059327373f, A0, A1, A2, A3, lane, tid4);

        layer64(U_W2, A0, A1, A2, A3, acc, lane);
        cvt_frag(acc, 0.125f, A0, A1, A2, A3, lane, tid4);

        layer64(U_W3, A0, A1, A2, A3, acc, lane);
        cvt_frag(acc, 0.125f, A0, A1, A2, A3, lane, tid4);

        int s0r = wSend[gid], s1r = wSend[gid + 8];
        bool last = (tile == 1);

        l4_chunk<1, 0>(U_W4 + 0 * 1024, A0, A1, A2, A3, s0r, s1r,
                       wMsg, wSh, wRecv, lane, gid, tid4, ncur, car0, last);
        l4_chunk<3, 1>(U_W4 + 1 * 1024, A0, A1, A2, A3, s0r, s1r,
                       wMsg, wSh, wRecv, lane, gid, tid4, ncur, car1, last);
        l4_chunk<5, 4>(U_W4 + 2 * 1024, A0, A1, A2, A3, s0r, s1r,
                       wMsg, wSh, wRecv, lane, gid, tid4, ncur, car2, last);

        ncur = wRecv[15];
        __syncwarp();
    }
}

// ---------------- launch 5: linear_down, 16 nodes/block (also re-zeroes g_agg) ----------------
template <int D, int KOFF, int OFF>
__device__ __forceinline__ void down_part(const float* __restrict__ sAg,
                                          const float* __restrict__ wrow,
                                          float* __restrict__ outn, int dch) {
    float acc[D];
#pragma unroll
    for (int m = 0; m < D; ++m) acc[m] = 0.f;
#pragma unroll
    for (int c4 = 0; c4 < 16; ++c4) {
        float4 w = *(const float4*)(wrow + c4 * 4);
#pragma unroll
        for (int m = 0; m < D; ++m) {
            float4 a = *(const float4*)(sAg + (KOFF + m) * 64 + c4 * 4);
            acc[m] += a.x * w.x + a.y * w.y + a.z * w.z + a.w * w.w;
        }
    }
#pragma unroll
    for (int m = 0; m < D; ++m)
        outn[OFF + dch * D + m] = acc[m] * 0.125f;
}

__global__ __launch_bounds__(256) void k_down(const float* __restrict__ Wd,
                                              float* __restrict__ out) {
    extern __shared__ float smf[];
    float* sWt = smf;                 // [192][68] = 13056
    float* sAg = smf + 13056;         // 16*576 = 9216
    int t = threadIdx.x;
    for (int idx = t; idx < 3 * 4096; idx += 256) {
        int l = idx >> 12, rem = idx & 4095, c = rem >> 6, dch = rem & 63;
        sWt[(l * 64 + dch) * 68 + c] = Wd[idx];
    }
    int nb = blockIdx.x * 16;
    float4* aggb = (float4*)(g_agg + (size_t)nb * 576);
    for (int idx = t; idx < 2304; idx += 256) {      // 16*576/4
        ((float4*)sAg)[idx] = aggb[idx];
        aggb[idx] = make_float4(0.f, 0.f, 0.f, 0.f); // restore invariant
    }
    __syncthreads();
    if (t < 192) {
        int l = t >> 6, dch = t & 63;
        const float* wrow = sWt + t * 68;
#pragma unroll 1
        for (int i = 0; i < 16; ++i) {
            const float* ag = sAg + i * 576;
            float* outn = out + (size_t)(nb + i) * 576;
            if (l == 0)      down_part<1, 0, 0>(ag, wrow, outn, dch);
            else if (l == 1) down_part<3, 1, 64>(ag, wrow, outn, dch);
            else             down_part<5, 4, 256>(ag, wrow, outn, dch);
        }
    }
}

// ---------------- launch ----------------
extern "C" void kernel_launch(void* const* d_in, const int* in_sizes, int n_in,
                              void* d_out, int out_size) {
    const float* evec = (const float*)d_in[0];
    const float* nf   = (const float*)d_in[1];
    const float* rad  = (const float*)d_in[2];
    const int* senders   = (const int*)d_in[3];
    const int* receivers = (const int*)d_in[4];
    const float* Wup = (const float*)d_in[5];
    const float* W1  = (const float*)d_in[6];
    const float* W2  = (const float*)d_in[7];
    const float* W3  = (const float*)d_in[8];
    const float* W4  = (const float*)d_in[9];
    const float* Wd  = (const float*)d_in[10];
    float* out = (float*)d_out;

    const int SMEM_DOWN = (13056 + 9216) * 4;         // 89088 B
    cudaFuncSetAttribute(k_down, cudaFuncAttributeMaxDynamicSharedMemorySize, SMEM_DOWN);

    k_count_h<<<1250 + 21, 256>>>(receivers, nf, Wup, W1, W2, W3, W4);
    k_scan<<<1, 1024>>>();
    k_fill<<<N_EDGES / 256, 256>>>(receivers, senders);
    k_edge<<<N_EDGES / 256, 256>>>(evec, rad);
    k_down<<<N_NODES / 16, 256, SMEM_DOWN>>>(Wd, out);
}

// round 11
// speedup vs baseline: 1.0743x; 1.0743x over previous
#include <cuda_runtime.h>
#include <cstdint>

#define N_NODES 10000
#define N_EDGES 320000

// ---------------- scratch (device globals; allocation-free) ----------------
__device__ float g_h[N_NODES * 64];                 // 2.56 MB
__device__ float g_agg[(size_t)N_NODES * 576];      // 23 MB; zeroed by k_down after read
__device__ int   g_count[N_NODES];                  // zeroed by k_scan after read
__device__ int   g_rowstart[N_NODES + 1];
__device__ int   g_cursor[N_NODES];
__device__ int   g_csr[N_EDGES];
__device__ int   g_send[N_EDGES];
__device__ int   g_recv[N_EDGES];
__device__ uint4 g_wfrag[5248];                     // fragment-ordered tf32 weights (84KB)

// uint4 offsets into g_wfrag
#define U_W1 0
#define U_W2 128
#define U_W3 1152
#define U_W4 2176       // + chunk*1024

__device__ __forceinline__ float silu_f(float x) {
    return __fdividef(x, 1.f + __expf(-x));
}

__device__ __forceinline__ uint32_t f2tf32(float f) {
    uint32_t r;
    asm("cvt.rna.tf32.f32 %0, %1;" : "=r"(r) : "f"(f));
    return r;
}

__device__ __forceinline__ void mma_tf32(float acc[4], uint32_t a0, uint32_t a1,
                                         uint32_t a2, uint32_t a3,
                                         uint32_t b0, uint32_t b1) {
    asm volatile(
        "mma.sync.aligned.m16n8k8.row.col.f32.tf32.tf32.f32 "
        "{%0,%1,%2,%3}, {%4,%5,%6,%7}, {%8,%9}, {%0,%1,%2,%3};\n"
        : "+f"(acc[0]), "+f"(acc[1]), "+f"(acc[2]), "+f"(acc[3])
        : "r"(a0), "r"(a1), "r"(a2), "r"(a3), "r"(b0), "r"(b1));
}

// fire-and-forget vector float2 reduction (sm_90+)
__device__ __forceinline__ void red2(float* p, float x, float y) {
    asm volatile("red.global.add.v2.f32 [%0], {%1, %2};"
                 :: "l"(p), "f"(x), "f"(y) : "memory");
}

// ---------------- launch 1: count histogram + h GEMM + (blocks>=1250) weight prep ----------------
__global__ __launch_bounds__(256) void k_count_h(const int* __restrict__ recv,
                                                 const float* __restrict__ nf,
                                                 const float* __restrict__ Wup,
                                                 const float* __restrict__ W1,
                                                 const float* __restrict__ W2,
                                                 const float* __restrict__ W3,
                                                 const float* __restrict__ W4) {
    int t = threadIdx.x;
    if (blockIdx.x >= 1250) {
        // weight prep: uint4 { tf32 W[k0][n0], W[k0+4][n0], W[k0][n1], W[k0+4][n1] }
        int u = (blockIdx.x - 1250) * 256 + t;
        if (u >= 5248) return;
        const float* src; int rs, co, KK, local;
        if (u < 128)       { src = W1; rs = 64;  co = 0;   KK = 1; local = u; }
        else if (u < 1152) { src = W2; rs = 64;  co = 0;   KK = 8; local = u - 128; }
        else if (u < 2176) { src = W3; rs = 64;  co = 0;   KK = 8; local = u - 1152; }
        else if (u < 3200) { src = W4; rs = 192; co = 0;   KK = 8; local = u - 2176; }
        else if (u < 4224) { src = W4; rs = 192; co = 64;  KK = 8; local = u - 3200; }
        else               { src = W4; rs = 192; co = 128; KK = 8; local = u - 4224; }
        int lane = local & 31; int rest = local >> 5;
        int np = rest & 1; rest >>= 1;
        int kk = rest % KK; int hb = rest / KK;
        int n0 = co + hb * 32 + np * 16 + (lane >> 2);
        int n1 = n0 + 8;
        int k0 = kk * 8 + (lane & 3);
        g_wfrag[u] = make_uint4(f2tf32(src[(size_t)k0 * rs + n0]),
                                f2tf32(src[(size_t)(k0 + 4) * rs + n0]),
                                f2tf32(src[(size_t)k0 * rs + n1]),
                                f2tf32(src[(size_t)(k0 + 4) * rs + n1]));
        return;
    }

    __shared__ float sW[64 * 64];
    __shared__ float sN[8 * 64];
    int e = blockIdx.x * 256 + t;
    atomicAdd(&g_count[recv[e]], 1);          // N_EDGES % 256 == 0

    for (int idx = t; idx < 1024; idx += 256)
        ((float4*)sW)[idx] = ((const float4*)Wup)[idx];
    int n0 = blockIdx.x * 8;                  // 1250 * 8 = 10000
    if (t < 128)
        ((float4*)sN)[t] = ((const float4*)(nf + (size_t)n0 * 64))[t];
    __syncthreads();

#pragma unroll
    for (int j = 0; j < 2; ++j) {
        int o = t + j * 256;
        int row = o >> 6, c = o & 63;
        float a0 = 0.f, a1 = 0.f;
#pragma unroll
        for (int k = 0; k < 64; k += 2) {
            a0 = fmaf(sN[row * 64 + k],     sW[k * 64 + c],       a0);
            a1 = fmaf(sN[row * 64 + k + 1], sW[(k + 1) * 64 + c], a1);
        }
        g_h[(size_t)(n0 + row) * 64 + c] = (a0 + a1) * 0.125f;
    }
}

// ---------------- launch 2: parallel exclusive scan (+ zero g_count) ----------------
__global__ __launch_bounds__(1024) void k_scan() {
    __shared__ int warpsum[32];
    int t = threadIdx.x, lane = t & 31, w = t >> 5;
    int base = t * 10;
    int c[10];
    int s = 0;
#pragma unroll
    for (int i = 0; i < 10; ++i) {
        int idx = base + i;
        c[i] = (idx < N_NODES) ? g_count[idx] : 0;
        s += c[i];
    }
    int pre = s;
#pragma unroll
    for (int d = 1; d < 32; d <<= 1) {
        int v = __shfl_up_sync(0xffffffffu, pre, d);
        if (lane >= d) pre += v;
    }
    if (lane == 31) warpsum[w] = pre;
    __syncthreads();
    if (w == 0) {
        int v = warpsum[lane];
#pragma unroll
        for (int d = 1; d < 32; d <<= 1) {
            int u = __shfl_up_sync(0xffffffffu, v, d);
            if (lane >= d) v += u;
        }
        warpsum[lane] = v;
    }
    __syncthreads();
    int wbase = (w > 0) ? warpsum[w - 1] : 0;
    int run = wbase + pre - s;
#pragma unroll
    for (int i = 0; i < 10; ++i) {
        int idx = base + i;
        if (idx < N_NODES) {
            g_rowstart[idx] = run;
            g_cursor[idx] = run;
            run += c[i];
            g_count[idx] = 0;
        }
    }
    if (t == 1023) g_rowstart[N_NODES] = warpsum[31];
}

// ---------------- launch 3: CSR fill ----------------
__global__ void k_fill(const int* __restrict__ recv, const int* __restrict__ send) {
    int e = blockIdx.x * blockDim.x + threadIdx.x;
    if (e < N_EDGES) {
        int r = recv[e];
        int pos = atomicAdd(&g_cursor[r], 1);
        g_csr[pos] = e;
        g_send[pos] = send[e];
        g_recv[pos] = r;
    }
}

// ---------------- launch 4 (profiled): warp-autonomous fused MLP + SH + TP + scatter ----------------
// Each warp owns 16 CSR positions end-to-end; activations in registers between
// layers (C-frag -> A-frag shuffle conversion); weights streamed as uint4;
// epilogue flushes via vector v2 reductions (lane owns channels 2l, 2l+1).

__device__ __forceinline__ void layer64(int base, const uint32_t A0[8],
                                        const uint32_t A1[8], const uint32_t A2[8],
                                        const uint32_t A3[8], float acc[8][4],
                                        int lane) {
#pragma unroll
    for (int j = 0; j < 8; ++j) {
        acc[j][0] = 0.f; acc[j][1] = 0.f; acc[j][2] = 0.f; acc[j][3] = 0.f;
    }
#pragma unroll
    for (int kk = 0; kk < 8; ++kk) {
#pragma unroll
        for (int hb = 0; hb < 2; ++hb) {
#pragma unroll
            for (int np = 0; np < 2; ++np) {
                uint4 b = __ldg(&g_wfrag[base + (((hb * 8 + kk) * 2 + np) * 32) + lane]);
                int j = hb * 4 + np * 2;
                mma_tf32(acc[j],     A0[kk], A1[kk], A2[kk], A3[kk], b.x, b.y);
                mma_tf32(acc[j + 1], A0[kk], A1[kk], A2[kk], A3[kk], b.z, b.w);
            }
        }
    }
}

// C-frag -> next layer A-frag conversion (scale + silu + tf32), via shuffles.
__device__ __forceinline__ void cvt_frag(const float acc[8][4], float scale,
                                         uint32_t A0[8], uint32_t A1[8],
                                         uint32_t A2[8], uint32_t A3[8],
                                         int lane, int tid4) {
    int src  = (lane & 28) | (tid4 >> 1);
    int src2 = src + 2;
    bool odd = (tid4 & 1);
#pragma unroll
    for (int j = 0; j < 8; ++j) {
        uint32_t c0 = f2tf32(silu_f(acc[j][0] * scale));
        uint32_t c1 = f2tf32(silu_f(acc[j][1] * scale));
        uint32_t c2 = f2tf32(silu_f(acc[j][2] * scale));
        uint32_t c3 = f2tf32(silu_f(acc[j][3] * scale));
        uint32_t s0 = __shfl_sync(0xffffffffu, c0, src);
        uint32_t s1 = __shfl_sync(0xffffffffu, c1, src);
        uint32_t s2 = __shfl_sync(0xffffffffu, c2, src);
        uint32_t s3 = __shfl_sync(0xffffffffu, c3, src);
        uint32_t u0 = __shfl_sync(0xffffffffu, c0, src2);
        uint32_t u1 = __shfl_sync(0xffffffffu, c1, src2);
        uint32_t u2 = __shfl_sync(0xffffffffu, c2, src2);
        uint32_t u3 = __shfl_sync(0xffffffffu, c3, src2);
        A0[j] = odd ? s1 : s0;
        A1[j] = odd ? s3 : s2;
        A2[j] = odd ? u1 : u0;
        A3[j] = odd ? u3 : u2;
    }
}

template <int D, int KOFF>
__device__ __forceinline__ void l4_chunk(int base, const uint32_t A0[8],
                                         const uint32_t A1[8], const uint32_t A2[8],
                                         const uint32_t A3[8],
                                         const float2 hf0[8], const float2 hf1[8],
                                         float* __restrict__ wMsg,
                                         const float* __restrict__ wSh,
                                         const int* __restrict__ wRecv,
                                         int lane, int gid, int tid4) {
    float acc[8][4];
    layer64(base, A0, A1, A2, A3, acc, lane);

    const float S = 1.f / 256.f;   // 1/sqrt(64) / avg_neigh
#pragma unroll
    for (int j = 0; j < 8; ++j) {
        int col = j * 8 + 2 * tid4;
        *(float2*)(wMsg + gid * 66 + col) =
            make_float2(acc[j][0] * hf0[j].x * S, acc[j][1] * hf0[j].y * S);
        *(float2*)(wMsg + (gid + 8) * 66 + col) =
            make_float2(acc[j][2] * hf1[j].x * S, acc[j][3] * hf1[j].y * S);
    }
    __syncwarp();

    // warp-local segment reduction: lane owns channels (2*lane, 2*lane+1)
    {
        int ncur = wRecv[0];
        float a[D][2];
#pragma unroll
        for (int k = 0; k < D; ++k) { a[k][0] = 0.f; a[k][1] = 0.f; }
#pragma unroll 4
        for (int r = 0; r < 16; ++r) {
            int n = wRecv[r];
            if (n != ncur) {
#pragma unroll
                for (int k = 0; k < D; ++k) {
                    red2(&g_agg[(size_t)(ncur * 9 + KOFF + k) * 64 + 2 * lane],
                         a[k][0], a[k][1]);
                    a[k][0] = 0.f; a[k][1] = 0.f;
                }
                ncur = n;
            }
            float2 m = *(const float2*)(wMsg + r * 66 + 2 * lane);
#pragma unroll
            for (int k = 0; k < D; ++k) {
                float s = wSh[r * 12 + KOFF + k];
                a[k][0] = fmaf(m.x, s, a[k][0]);
                a[k][1] = fmaf(m.y, s, a[k][1]);
            }
        }
#pragma unroll
        for (int k = 0; k < D; ++k)
            red2(&g_agg[(size_t)(ncur * 9 + KOFF + k) * 64 + 2 * lane],
                 a[k][0], a[k][1]);
    }
    __syncwarp();
}

__global__ __launch_bounds__(256, 2) void k_edge(const float* __restrict__ evec,
                                                 const float* __restrict__ rad) {
    __shared__ __align__(16) float sMsgAll[8][16 * 66];   // 33792 B
    __shared__ __align__(16) float sShAll[8][16 * 12];    // 6144 B
    __shared__ int sMeta[8][32];                          // 1024 B

    int t = threadIdx.x, lane = t & 31, warp = t >> 5;
    int gid = lane >> 2, tid4 = lane & 3;
    float* wMsg = sMsgAll[warp];
    float* wSh  = sShAll[warp];
    int* wRecv  = sMeta[warp];
    int* wSend  = sMeta[warp] + 16;
    int pos0 = blockIdx.x * 128 + warp * 16;

    // init: lanes 0..15 handle one row each (SH + meta)
    if (lane < 16) {
        int pos = pos0 + lane;
        int e = g_csr[pos];
        wRecv[lane] = g_recv[pos];
        wSend[lane] = g_send[pos];
        float x = evec[(size_t)e * 3], y = evec[(size_t)e * 3 + 1],
              z = evec[(size_t)e * 3 + 2];
        float rn = rsqrtf(x * x + y * y + z * z);
        x *= rn; y *= rn; z *= rn;
        const float c3  = 1.7320508075688772f;
        const float c15 = 3.872983346207417f;
        const float c5h = 1.118033988749895f;
        const float c15h= 1.9364916731037085f;
        float* o = wSh + lane * 12;
        o[0] = 1.f;
        o[1] = c3 * x; o[2] = c3 * y; o[3] = c3 * z;
        o[4] = c15 * x * y; o[5] = c15 * y * z;
        o[6] = c5h * (3.f * z * z - 1.f);
        o[7] = c15 * x * z; o[8] = c15h * (x * x - y * y);
    }
    __syncwarp();

    // L1 A-fragments straight from rad (rows gid, gid+8; cols tid4, tid4+4)
    int e0 = g_csr[pos0 + gid], e1 = g_csr[pos0 + gid + 8];
    uint32_t r0 = f2tf32(__ldg(rad + (size_t)e0 * 8 + tid4));
    uint32_t r1 = f2tf32(__ldg(rad + (size_t)e1 * 8 + tid4));
    uint32_t r2 = f2tf32(__ldg(rad + (size_t)e0 * 8 + tid4 + 4));
    uint32_t r3 = f2tf32(__ldg(rad + (size_t)e1 * 8 + tid4 + 4));

    float acc[8][4];
    uint32_t A0[8], A1[8], A2[8], A3[8];

    // L1: [16,8]@[8,64] — 4 uint4 weight loads
#pragma unroll
    for (int j = 0; j < 8; ++j) {
        acc[j][0] = 0.f; acc[j][1] = 0.f; acc[j][2] = 0.f; acc[j][3] = 0.f;
    }
#pragma unroll
    for (int hb = 0; hb < 2; ++hb)
#pragma unroll
        for (int np = 0; np < 2; ++np) {
            uint4 b = __ldg(&g_wfrag[U_W1 + ((hb * 2 + np) * 32) + lane]);
            int j = hb * 4 + np * 2;
            mma_tf32(acc[j],     r0, r1, r2, r3, b.x, b.y);
            mma_tf32(acc[j + 1], r0, r1, r2, r3, b.z, b.w);
        }
    cvt_frag(acc, 0.35355339059327373f, A0, A1, A2, A3, lane, tid4);

    // L2
    layer64(U_W2, A0, A1, A2, A3, acc, lane);
    cvt_frag(acc, 0.125f, A0, A1, A2, A3, lane, tid4);

    // L3
    layer64(U_W3, A0, A1, A2, A3, acc, lane);
    cvt_frag(acc, 0.125f, A0, A1, A2, A3, lane, tid4);

    // h fragments (register-resident across all 3 chunks)
    int s0r = wSend[gid], s1r = wSend[gid + 8];
    float2 hf0[8], hf1[8];
#pragma unroll
    for (int j = 0; j < 8; ++j) {
        hf0[j] = *(const float2*)(g_h + (size_t)s0r * 64 + j * 8 + 2 * tid4);
        hf1[j] = *(const float2*)(g_h + (size_t)s1r * 64 + j * 8 + 2 * tid4);
    }

    // L4 chunks + tensor product + warp-local segment scatter
    l4_chunk<1, 0>(U_W4 + 0 * 1024, A0, A1, A2, A3, hf0, hf1,
                   wMsg, wSh, wRecv, lane, gid, tid4);
    l4_chunk<3, 1>(U_W4 + 1 * 1024, A0, A1, A2, A3, hf0, hf1,
                   wMsg, wSh, wRecv, lane, gid, tid4);
    l4_chunk<5, 4>(U_W4 + 2 * 1024, A0, A1, A2, A3, hf0, hf1,
                   wMsg, wSh, wRecv, lane, gid, tid4);
}

// ---------------- launch 5: linear_down, 16 nodes/block (also re-zeroes g_agg) ----------------
template <int D, int KOFF, int OFF>
__device__ __forceinline__ void down_part(const float* __restrict__ sAg,
                                          const float* __restrict__ wrow,
                                          float* __restrict__ outn, int dch) {
    float acc[D];
#pragma unroll
    for (int m = 0; m < D; ++m) acc[m] = 0.f;
#pragma unroll
    for (int c4 = 0; c4 < 16; ++c4) {
        float4 w = *(const float4*)(wrow + c4 * 4);
#pragma unroll
        for (int m = 0; m < D; ++m) {
            float4 a = *(const float4*)(sAg + (KOFF + m) * 64 + c4 * 4);
            acc[m] += a.x * w.x + a.y * w.y + a.z * w.z + a.w * w.w;
        }
    }
#pragma unroll
    for (int m = 0; m < D; ++m)
        outn[OFF + dch * D + m] = acc[m] * 0.125f;
}

__global__ __launch_bounds__(256) void k_down(const float* __restrict__ Wd,
                                              float* __restrict__ out) {
    extern __shared__ float smf[];
    float* sWt = smf;                 // [192][68] = 13056
    float* sAg = smf + 13056;         // 16*576 = 9216
    int t = threadIdx.x;
    for (int idx = t; idx < 3 * 4096; idx += 256) {
        int l = idx >> 12, rem = idx & 4095, c = rem >> 6, dch = rem & 63;
        sWt[(l * 64 + dch) * 68 + c] = Wd[idx];
    }
    int nb = blockIdx.x * 16;
    float4* aggb = (float4*)(g_agg + (size_t)nb * 576);
    for (int idx = t; idx < 2304; idx += 256) {      // 16*576/4
        ((float4*)sAg)[idx] = aggb[idx];
        aggb[idx] = make_float4(0.f, 0.f, 0.f, 0.f); // restore invariant
    }
    __syncthreads();
    if (t < 192) {
        int l = t >> 6, dch = t & 63;
        const float* wrow = sWt + t * 68;
#pragma unroll 1
        for (int i = 0; i < 16; ++i) {
            const float* ag = sAg + i * 576;
            float* outn = out + (size_t)(nb + i) * 576;
            if (l == 0)      down_part<1, 0, 0>(ag, wrow, outn, dch);
            else if (l == 1) down_part<3, 1, 64>(ag, wrow, outn, dch);
            else             down_part<5, 4, 256>(ag, wrow, outn, dch);
        }
    }
}

// ---------------- launch ----------------
extern "C" void kernel_launch(void* const* d_in, const int* in_sizes, int n_in,
                              void* d_out, int out_size) {
    const float* evec = (const float*)d_in[0];
    const float* nf   = (const float*)d_in[1];
    const float* rad  = (const float*)d_in[2];
    const int* senders   = (const int*)d_in[3];
    const int* receivers = (const int*)d_in[4];
    const float* Wup = (const float*)d_in[5];
    const float* W1  = (const float*)d_in[6];
    const float* W2  = (const float*)d_in[7];
    const float* W3  = (const float*)d_in[8];
    const float* W4  = (const float*)d_in[9];
    const float* Wd  = (const float*)d_in[10];
    float* out = (float*)d_out;

    const int SMEM_DOWN = (13056 + 9216) * 4;         // 89088 B
    cudaFuncSetAttribute(k_down, cudaFuncAttributeMaxDynamicSharedMemorySize, SMEM_DOWN);

    k_count_h<<<1250 + 21, 256>>>(receivers, nf, Wup, W1, W2, W3, W4);
    k_scan<<<1, 1024>>>();
    k_fill<<<N_EDGES / 256, 256>>>(receivers, senders);
    k_edge<<<N_EDGES / 128, 256>>>(evec, rad);
    k_down<<<N_NODES / 16, 256, SMEM_DOWN>>>(Wd, out);
}

// round 12
// speedup vs baseline: 1.5021x; 1.3982x over previous
#include <cuda_runtime.h>
#include <cstdint>

#define N_NODES 10000
#define N_EDGES 320000

// ---------------- scratch (device globals; allocation-free) ----------------
__device__ float g_h[N_NODES * 64];                 // 2.56 MB
__device__ float g_agg[(size_t)N_NODES * 576];      // 23 MB; zeroed by k_count_h each call
__device__ int   g_count[N_NODES];                  // zeroed by k_scan after read
__device__ int   g_rowstart[N_NODES + 1];
__device__ int   g_cursor[N_NODES];
__device__ int   g_csr[N_EDGES];
__device__ int   g_send[N_EDGES];
__device__ int   g_recv[N_EDGES];
__device__ uint4 g_wfrag[8320];                     // fragment-ordered tf32 weights (133KB)

// uint4 offsets into g_wfrag
#define U_W1 0
#define U_W2 128
#define U_W3 1152
#define U_W4 2176       // + chunk*1024
#define U_WD 5248       // + l*1024

__device__ __forceinline__ float silu_f(float x) {
    return __fdividef(x, 1.f + __expf(-x));
}

__device__ __forceinline__ uint32_t f2tf32(float f) {
    uint32_t r;
    asm("cvt.rna.tf32.f32 %0, %1;" : "=r"(r) : "f"(f));
    return r;
}

__device__ __forceinline__ void mma_tf32(float acc[4], uint32_t a0, uint32_t a1,
                                         uint32_t a2, uint32_t a3,
                                         uint32_t b0, uint32_t b1) {
    asm volatile(
        "mma.sync.aligned.m16n8k8.row.col.f32.tf32.tf32.f32 "
        "{%0,%1,%2,%3}, {%4,%5,%6,%7}, {%8,%9}, {%0,%1,%2,%3};\n"
        : "+f"(acc[0]), "+f"(acc[1]), "+f"(acc[2]), "+f"(acc[3])
        : "r"(a0), "r"(a1), "r"(a2), "r"(a3), "r"(b0), "r"(b1));
}

// fire-and-forget vector float2 reduction (sm_90+)
__device__ __forceinline__ void red2(float* p, float x, float y) {
    asm volatile("red.global.add.v2.f32 [%0], {%1, %2};"
                 :: "l"(p), "f"(x), "f"(y) : "memory");
}

// ---------------- launch 1: count histogram + h GEMM + agg zero + weight prep ----------------
__global__ __launch_bounds__(256) void k_count_h(const int* __restrict__ recv,
                                                 const float* __restrict__ nf,
                                                 const float* __restrict__ Wup,
                                                 const float* __restrict__ W1,
                                                 const float* __restrict__ W2,
                                                 const float* __restrict__ W3,
                                                 const float* __restrict__ W4,
                                                 const float* __restrict__ Wd) {
    int t = threadIdx.x;
    if (blockIdx.x >= 1250) {
        // weight prep: uint4 { tf32 W[k0][n0], W[k0+4][n0], W[k0][n1], W[k0+4][n1] }
        int u = (blockIdx.x - 1250) * 256 + t;
        if (u >= 8320) return;
        const float* src; int rs, co, KK, local;
        if (u < 128)       { src = W1; rs = 64;  co = 0;   KK = 1; local = u; }
        else if (u < 1152) { src = W2; rs = 64;  co = 0;   KK = 8; local = u - 128; }
        else if (u < 2176) { src = W3; rs = 64;  co = 0;   KK = 8; local = u - 1152; }
        else if (u < 3200) { src = W4; rs = 192; co = 0;   KK = 8; local = u - 2176; }
        else if (u < 4224) { src = W4; rs = 192; co = 64;  KK = 8; local = u - 3200; }
        else if (u < 5248) { src = W4; rs = 192; co = 128; KK = 8; local = u - 4224; }
        else               { int v = u - 5248; src = Wd + (v >> 10) * 4096;
                             rs = 64; co = 0; KK = 8; local = v & 1023; }
        int lane = local & 31; int rest = local >> 5;
        int np = rest & 1; rest >>= 1;
        int kk = rest % KK; int hb = rest / KK;
        int n0 = co + hb * 32 + np * 16 + (lane >> 2);
        int n1 = n0 + 8;
        int k0 = kk * 8 + (lane & 3);
        g_wfrag[u] = make_uint4(f2tf32(src[(size_t)k0 * rs + n0]),
                                f2tf32(src[(size_t)(k0 + 4) * rs + n0]),
                                f2tf32(src[(size_t)k0 * rs + n1]),
                                f2tf32(src[(size_t)(k0 + 4) * rs + n1]));
        return;
    }

    // zero this block's slice of g_agg (1250 * 1152 float4 = 10000*576 floats)
    {
        float4* aggb = (float4*)g_agg + (size_t)blockIdx.x * 1152;
        for (int i = t; i < 1152; i += 256)
            aggb[i] = make_float4(0.f, 0.f, 0.f, 0.f);
    }

    __shared__ float sW[64 * 64];
    __shared__ float sN[8 * 64];
    int e = blockIdx.x * 256 + t;
    atomicAdd(&g_count[recv[e]], 1);          // N_EDGES % 256 == 0

    for (int idx = t; idx < 1024; idx += 256)
        ((float4*)sW)[idx] = ((const float4*)Wup)[idx];
    int n0 = blockIdx.x * 8;                  // 1250 * 8 = 10000
    if (t < 128)
        ((float4*)sN)[t] = ((const float4*)(nf + (size_t)n0 * 64))[t];
    __syncthreads();

#pragma unroll
    for (int j = 0; j < 2; ++j) {
        int o = t + j * 256;
        int row = o >> 6, c = o & 63;
        float a0 = 0.f, a1 = 0.f;
#pragma unroll
        for (int k = 0; k < 64; k += 2) {
            a0 = fmaf(sN[row * 64 + k],     sW[k * 64 + c],       a0);
            a1 = fmaf(sN[row * 64 + k + 1], sW[(k + 1) * 64 + c], a1);
        }
        g_h[(size_t)(n0 + row) * 64 + c] = (a0 + a1) * 0.125f;
    }
}

// ---------------- launch 2: parallel exclusive scan (+ zero g_count) ----------------
__global__ __launch_bounds__(1024) void k_scan() {
    __shared__ int warpsum[32];
    int t = threadIdx.x, lane = t & 31, w = t >> 5;
    int base = t * 10;
    int c[10];
    int s = 0;
#pragma unroll
    for (int i = 0; i < 10; ++i) {
        int idx = base + i;
        c[i] = (idx < N_NODES) ? g_count[idx] : 0;
        s += c[i];
    }
    int pre = s;
#pragma unroll
    for (int d = 1; d < 32; d <<= 1) {
        int v = __shfl_up_sync(0xffffffffu, pre, d);
        if (lane >= d) pre += v;
    }
    if (lane == 31) warpsum[w] = pre;
    __syncthreads();
    if (w == 0) {
        int v = warpsum[lane];
#pragma unroll
        for (int d = 1; d < 32; d <<= 1) {
            int u = __shfl_up_sync(0xffffffffu, v, d);
            if (lane >= d) v += u;
        }
        warpsum[lane] = v;
    }
    __syncthreads();
    int wbase = (w > 0) ? warpsum[w - 1] : 0;
    int run = wbase + pre - s;
#pragma unroll
    for (int i = 0; i < 10; ++i) {
        int idx = base + i;
        if (idx < N_NODES) {
            g_rowstart[idx] = run;
            g_cursor[idx] = run;
            run += c[i];
            g_count[idx] = 0;
        }
    }
    if (t == 1023) g_rowstart[N_NODES] = warpsum[31];
}

// ---------------- launch 3: CSR fill ----------------
__global__ void k_fill(const int* __restrict__ recv, const int* __restrict__ send) {
    int e = blockIdx.x * blockDim.x + threadIdx.x;
    if (e < N_EDGES) {
        int r = recv[e];
        int pos = atomicAdd(&g_cursor[r], 1);
        g_csr[pos] = e;
        g_send[pos] = send[e];
        g_recv[pos] = r;
    }
}

// ---------------- launch 4 (profiled): warp-autonomous fused MLP + SH + TP + scatter ----------------
// Each warp owns 16 CSR positions end-to-end; activations in registers between
// layers (C-frag -> A-frag shuffle conversion); weights streamed as uint4;
// epilogue flushes via vector v2 reductions (lane owns channels 2l, 2l+1).

__device__ __forceinline__ void layer64(int base, const uint32_t A0[8],
                                        const uint32_t A1[8], const uint32_t A2[8],
                                        const uint32_t A3[8], float acc[8][4],
                                        int lane) {
#pragma unroll
    for (int j = 0; j < 8; ++j) {
        acc[j][0] = 0.f; acc[j][1] = 0.f; acc[j][2] = 0.f; acc[j][3] = 0.f;
    }
#pragma unroll
    for (int kk = 0; kk < 8; ++kk) {
#pragma unroll
        for (int hb = 0; hb < 2; ++hb) {
#pragma unroll
            for (int np = 0; np < 2; ++np) {
                uint4 b = __ldg(&g_wfrag[base + (((hb * 8 + kk) * 2 + np) * 32) + lane]);
                int j = hb * 4 + np * 2;
                mma_tf32(acc[j],     A0[kk], A1[kk], A2[kk], A3[kk], b.x, b.y);
                mma_tf32(acc[j + 1], A0[kk], A1[kk], A2[kk], A3[kk], b.z, b.w);
            }
        }
    }
}

// C-frag -> next layer A-frag conversion (scale + silu + tf32), via shuffles.
__device__ __forceinline__ void cvt_frag(const float acc[8][4], float scale,
                                         uint32_t A0[8], uint32_t A1[8],
                                         uint32_t A2[8], uint32_t A3[8],
                                         int lane, int tid4) {
    int src  = (lane & 28) | (tid4 >> 1);
    int src2 = src + 2;
    bool odd = (tid4 & 1);
#pragma unroll
    for (int j = 0; j < 8; ++j) {
        uint32_t c0 = f2tf32(silu_f(acc[j][0] * scale));
        uint32_t c1 = f2tf32(silu_f(acc[j][1] * scale));
        uint32_t c2 = f2tf32(silu_f(acc[j][2] * scale));
        uint32_t c3 = f2tf32(silu_f(acc[j][3] * scale));
        uint32_t s0 = __shfl_sync(0xffffffffu, c0, src);
        uint32_t s1 = __shfl_sync(0xffffffffu, c1, src);
        uint32_t s2 = __shfl_sync(0xffffffffu, c2, src);
        uint32_t s3 = __shfl_sync(0xffffffffu, c3, src);
        uint32_t u0 = __shfl_sync(0xffffffffu, c0, src2);
        uint32_t u1 = __shfl_sync(0xffffffffu, c1, src2);
        uint32_t u2 = __shfl_sync(0xffffffffu, c2, src2);
        uint32_t u3 = __shfl_sync(0xffffffffu, c3, src2);
        A0[j] = odd ? s1 : s0;
        A1[j] = odd ? s3 : s2;
        A2[j] = odd ? u1 : u0;
        A3[j] = odd ? u3 : u2;
    }
}

template <int D, int KOFF>
__device__ __forceinline__ void l4_chunk(int base, const uint32_t A0[8],
                                         const uint32_t A1[8], const uint32_t A2[8],
                                         const uint32_t A3[8],
                                         const float2 hf0[8], const float2 hf1[8],
                                         float* __restrict__ wMsg,
                                         const float* __restrict__ wSh,
                                         const int* __restrict__ wRecv,
                                         int lane, int gid, int tid4) {
    float acc[8][4];
    layer64(base, A0, A1, A2, A3, acc, lane);

    const float S = 1.f / 256.f;   // 1/sqrt(64) / avg_neigh
#pragma unroll
    for (int j = 0; j < 8; ++j) {
        int col = j * 8 + 2 * tid4;
        *(float2*)(wMsg + gid * 66 + col) =
            make_float2(acc[j][0] * hf0[j].x * S, acc[j][1] * hf0[j].y * S);
        *(float2*)(wMsg + (gid + 8) * 66 + col) =
            make_float2(acc[j][2] * hf1[j].x * S, acc[j][3] * hf1[j].y * S);
    }
    __syncwarp();

    // warp-local segment reduction: lane owns channels (2*lane, 2*lane+1)
    {
        int ncur = wRecv[0];
        float a[D][2];
#pragma unroll
        for (int k = 0; k < D; ++k) { a[k][0] = 0.f; a[k][1] = 0.f; }
#pragma unroll 4
        for (int r = 0; r < 16; ++r) {
            int n = wRecv[r];
            if (n != ncur) {
#pragma unroll
                for (int k = 0; k < D; ++k) {
                    red2(&g_agg[(size_t)(ncur * 9 + KOFF + k) * 64 + 2 * lane],
                         a[k][0], a[k][1]);
                    a[k][0] = 0.f; a[k][1] = 0.f;
                }
                ncur = n;
            }
            float2 m = *(const float2*)(wMsg + r * 66 + 2 * lane);
#pragma unroll
            for (int k = 0; k < D; ++k) {
                float s = wSh[r * 12 + KOFF + k];
                a[k][0] = fmaf(m.x, s, a[k][0]);
                a[k][1] = fmaf(m.y, s, a[k][1]);
            }
        }
#pragma unroll
        for (int k = 0; k < D; ++k)
            red2(&g_agg[(size_t)(ncur * 9 + KOFF + k) * 64 + 2 * lane],
                 a[k][0], a[k][1]);
    }
    __syncwarp();
}

__global__ __launch_bounds__(256, 2) void k_edge(const float* __restrict__ evec,
                                                 const float* __restrict__ rad) {
    __shared__ __align__(16) float sMsgAll[8][16 * 66];   // 33792 B
    __shared__ __align__(16) float sShAll[8][16 * 12];    // 6144 B
    __shared__ int sMeta[8][32];                          // 1024 B

    int t = threadIdx.x, lane = t & 31, warp = t >> 5;
    int gid = lane >> 2, tid4 = lane & 3;
    float* wMsg = sMsgAll[warp];
    float* wSh  = sShAll[warp];
    int* wRecv  = sMeta[warp];
    int* wSend  = sMeta[warp] + 16;
    int pos0 = blockIdx.x * 128 + warp * 16;

    // init: lanes 0..15 handle one row each (SH + meta)
    if (lane < 16) {
        int pos = pos0 + lane;
        int e = g_csr[pos];
        wRecv[lane] = g_recv[pos];
        wSend[lane] = g_send[pos];
        float x = evec[(size_t)e * 3], y = evec[(size_t)e * 3 + 1],
              z = evec[(size_t)e * 3 + 2];
        float rn = rsqrtf(x * x + y * y + z * z);
        x *= rn; y *= rn; z *= rn;
        const float c3  = 1.7320508075688772f;
        const float c15 = 3.872983346207417f;
        const float c5h = 1.118033988749895f;
        const float c15h= 1.9364916731037085f;
        float* o = wSh + lane * 12;
        o[0] = 1.f;
        o[1] = c3 * x; o[2] = c3 * y; o[3] = c3 * z;
        o[4] = c15 * x * y; o[5] = c15 * y * z;
        o[6] = c5h * (3.f * z * z - 1.f);
        o[7] = c15 * x * z; o[8] = c15h * (x * x - y * y);
    }
    __syncwarp();

    // L1 A-fragments straight from rad (rows gid, gid+8; cols tid4, tid4+4)
    int e0 = g_csr[pos0 + gid], e1 = g_csr[pos0 + gid + 8];
    uint32_t r0 = f2tf32(__ldg(rad + (size_t)e0 * 8 + tid4));
    uint32_t r1 = f2tf32(__ldg(rad + (size_t)e1 * 8 + tid4));
    uint32_t r2 = f2tf32(__ldg(rad + (size_t)e0 * 8 + tid4 + 4));
    uint32_t r3 = f2tf32(__ldg(rad + (size_t)e1 * 8 + tid4 + 4));

    float acc[8][4];
    uint32_t A0[8], A1[8], A2[8], A3[8];

    // L1: [16,8]@[8,64] — 4 uint4 weight loads
#pragma unroll
    for (int j = 0; j < 8; ++j) {
        acc[j][0] = 0.f; acc[j][1] = 0.f; acc[j][2] = 0.f; acc[j][3] = 0.f;
    }
#pragma unroll
    for (int hb = 0; hb < 2; ++hb)
#pragma unroll
        for (int np = 0; np < 2; ++np) {
            uint4 b = __ldg(&g_wfrag[U_W1 + ((hb * 2 + np) * 32) + lane]);
            int j = hb * 4 + np * 2;
            mma_tf32(acc[j],     r0, r1, r2, r3, b.x, b.y);
            mma_tf32(acc[j + 1], r0, r1, r2, r3, b.z, b.w);
        }
    cvt_frag(acc, 0.35355339059327373f, A0, A1, A2, A3, lane, tid4);

    // L2
    layer64(U_W2, A0, A1, A2, A3, acc, lane);
    cvt_frag(acc, 0.125f, A0, A1, A2, A3, lane, tid4);

    // L3
    layer64(U_W3, A0, A1, A2, A3, acc, lane);
    cvt_frag(acc, 0.125f, A0, A1, A2, A3, lane, tid4);

    // h fragments (register-resident across all 3 chunks)
    int s0r = wSend[gid], s1r = wSend[gid + 8];
    float2 hf0[8], hf1[8];
#pragma unroll
    for (int j = 0; j < 8; ++j) {
        hf0[j] = *(const float2*)(g_h + (size_t)s0r * 64 + j * 8 + 2 * tid4);
        hf1[j] = *(const float2*)(g_h + (size_t)s1r * 64 + j * 8 + 2 * tid4);
    }

    // L4 chunks + tensor product + warp-local segment scatter
    l4_chunk<1, 0>(U_W4 + 0 * 1024, A0, A1, A2, A3, hf0, hf1,
                   wMsg, wSh, wRecv, lane, gid, tid4);
    l4_chunk<3, 1>(U_W4 + 1 * 1024, A0, A1, A2, A3, hf0, hf1,
                   wMsg, wSh, wRecv, lane, gid, tid4);
    l4_chunk<5, 4>(U_W4 + 2 * 1024, A0, A1, A2, A3, hf0, hf1,
                   wMsg, wSh, wRecv, lane, gid, tid4);
}

// ---------------- launch 5: linear_down as warp-autonomous tf32 MMA ----------------
// Row space per l: (node, m) pairs: l=0 -> 10000 rows, l=1 -> 30000, l=2 -> 50000.
// 16-row tiles: 625 + 1875 + 3125 = 5625 warps. No smem, no barriers, no atomics.
template <int D, int KOFF, int OFF>
__device__ __forceinline__ void down_tile(int tile, int wbase, float* __restrict__ out,
                                          int lane, int gid, int tid4) {
    int R0 = tile * 16 + gid, R1 = R0 + 8;
    int n0, m0, n1, m1;
    if (D == 1) { n0 = R0; m0 = 0; n1 = R1; m1 = 0; }
    else {
        n0 = R0 / D; m0 = R0 - n0 * D;
        n1 = R1 / D; m1 = R1 - n1 * D;
    }
    const float* p0 = g_agg + (size_t)n0 * 576 + (KOFF + m0) * 64;
    const float* p1 = g_agg + (size_t)n1 * 576 + (KOFF + m1) * 64;

    float acc[8][4];
#pragma unroll
    for (int j = 0; j < 8; ++j) {
        acc[j][0] = 0.f; acc[j][1] = 0.f; acc[j][2] = 0.f; acc[j][3] = 0.f;
    }
#pragma unroll
    for (int kk = 0; kk < 8; ++kk) {
        int c0 = kk * 8 + tid4;
        uint32_t a0 = f2tf32(__ldg(p0 + c0));
        uint32_t a1 = f2tf32(__ldg(p1 + c0));
        uint32_t a2 = f2tf32(__ldg(p0 + c0 + 4));
        uint32_t a3 = f2tf32(__ldg(p1 + c0 + 4));
#pragma unroll
        for (int hb = 0; hb < 2; ++hb)
#pragma unroll
            for (int np = 0; np < 2; ++np) {
                uint4 b = __ldg(&g_wfrag[wbase + (((hb * 8 + kk) * 2 + np) * 32) + lane]);
                int j = hb * 4 + np * 2;
                mma_tf32(acc[j],     a0, a1, a2, a3, b.x, b.y);
                mma_tf32(acc[j + 1], a0, a1, a2, a3, b.z, b.w);
            }
    }

    float* o0 = out + (size_t)n0 * 576 + OFF + m0;
    float* o1 = out + (size_t)n1 * 576 + OFF + m1;
#pragma unroll
    for (int j = 0; j < 8; ++j) {
        int dch = j * 8 + 2 * tid4;
        o0[dch * D]       = acc[j][0] * 0.125f;
        o0[(dch + 1) * D] = acc[j][1] * 0.125f;
        o1[dch * D]       = acc[j][2] * 0.125f;
        o1[(dch + 1) * D] = acc[j][3] * 0.125f;
    }
}

__global__ __launch_bounds__(256) void k_down(float* __restrict__ out) {
    int t = threadIdx.x, lane = t & 31, warp = t >> 5;
    int gid = lane >> 2, tid4 = lane & 3;
    int W = blockIdx.x * 8 + warp;
    if (W < 625)
        down_tile<1, 0, 0>(W, U_WD, out, lane, gid, tid4);
    else if (W < 2500)
        down_tile<3, 1, 64>(W - 625, U_WD + 1024, out, lane, gid, tid4);
    else if (W < 5625)
        down_tile<5, 4, 256>(W - 2500, U_WD + 2048, out, lane, gid, tid4);
}

// ---------------- launch ----------------
extern "C" void kernel_launch(void* const* d_in, const int* in_sizes, int n_in,
                              void* d_out, int out_size) {
    const float* evec = (const float*)d_in[0];
    const float* nf   = (const float*)d_in[1];
    const float* rad  = (const float*)d_in[2];
    const int* senders   = (const int*)d_in[3];
    const int* receivers = (const int*)d_in[4];
    const float* Wup = (const float*)d_in[5];
    const float* W1  = (const float*)d_in[6];
    const float* W2  = (const float*)d_in[7];
    const float* W3  = (const float*)d_in[8];
    const float* W4  = (const float*)d_in[9];
    const float* Wd  = (const float*)d_in[10];
    float* out = (float*)d_out;

    k_count_h<<<1250 + 33, 256>>>(receivers, nf, Wup, W1, W2, W3, W4, Wd);
    k_scan<<<1, 1024>>>();
    k_fill<<<N_EDGES / 256, 256>>>(receivers, senders);
    k_edge<<<N_EDGES / 128, 256>>>(evec, rad);
    k_down<<<704, 256>>>(out);
}

// round 13
// speedup vs baseline: 1.5023x; 1.0002x over previous
#include <cuda_runtime.h>
#include <cstdint>

#define N_NODES 10000
#define N_EDGES 320000

// ---------------- scratch (device globals; allocation-free) ----------------
__device__ float g_h[N_NODES * 64];                 // 2.56 MB
__device__ float g_agg[(size_t)N_NODES * 576];      // 23 MB; zeroed by k_fill_plus each call
__device__ int   g_count[N_NODES];                  // zeroed by k_scan after read
__device__ int   g_rowstart[N_NODES + 1];
__device__ int   g_cursor[N_NODES];
__device__ int   g_csr[N_EDGES];
__device__ int   g_send[N_EDGES];
__device__ int   g_recv[N_EDGES];
__device__ uint4 g_wfrag[8320];                     // fragment-ordered tf32 weights (133KB)

// uint4 offsets into g_wfrag
#define U_W1 0
#define U_W2 128
#define U_W3 1152
#define U_W4 2176       // + chunk*1024
#define U_WD 5248       // + l*1024

__device__ __forceinline__ float silu_f(float x) {
    return __fdividef(x, 1.f + __expf(-x));
}

__device__ __forceinline__ uint32_t f2tf32(float f) {
    uint32_t r;
    asm("cvt.rna.tf32.f32 %0, %1;" : "=r"(r) : "f"(f));
    return r;
}

__device__ __forceinline__ void mma_tf32(float acc[4], uint32_t a0, uint32_t a1,
                                         uint32_t a2, uint32_t a3,
                                         uint32_t b0, uint32_t b1) {
    asm volatile(
        "mma.sync.aligned.m16n8k8.row.col.f32.tf32.tf32.f32 "
        "{%0,%1,%2,%3}, {%4,%5,%6,%7}, {%8,%9}, {%0,%1,%2,%3};\n"
        : "+f"(acc[0]), "+f"(acc[1]), "+f"(acc[2]), "+f"(acc[3])
        : "r"(a0), "r"(a1), "r"(a2), "r"(a3), "r"(b0), "r"(b1));
}

// fire-and-forget vector float2 reduction (sm_90+)
__device__ __forceinline__ void red2(float* p, float x, float y) {
    asm volatile("red.global.add.v2.f32 [%0], {%1, %2};"
                 :: "l"(p), "f"(x), "f"(y) : "memory");
}

// ---------------- launch 1: edge count histogram ONLY (unblocks scan ASAP) ----------------
__global__ __launch_bounds__(256) void k_hist(const int* __restrict__ recv) {
    int e = blockIdx.x * 256 + threadIdx.x;
    atomicAdd(&g_count[recv[e]], 1);          // N_EDGES % 256 == 0
}

// ---------------- launch 2: parallel exclusive scan (+ zero g_count) ----------------
__global__ __launch_bounds__(1024) void k_scan() {
    __shared__ int warpsum[32];
    int t = threadIdx.x, lane = t & 31, w = t >> 5;
    int base = t * 10;
    int c[10];
    int s = 0;
#pragma unroll
    for (int i = 0; i < 10; ++i) {
        int idx = base + i;
        c[i] = (idx < N_NODES) ? g_count[idx] : 0;
        s += c[i];
    }
    int pre = s;
#pragma unroll
    for (int d = 1; d < 32; d <<= 1) {
        int v = __shfl_up_sync(0xffffffffu, pre, d);
        if (lane >= d) pre += v;
    }
    if (lane == 31) warpsum[w] = pre;
    __syncthreads();
    if (w == 0) {
        int v = warpsum[lane];
#pragma unroll
        for (int d = 1; d < 32; d <<= 1) {
            int u = __shfl_up_sync(0xffffffffu, v, d);
            if (lane >= d) v += u;
        }
        warpsum[lane] = v;
    }
    __syncthreads();
    int wbase = (w > 0) ? warpsum[w - 1] : 0;
    int run = wbase + pre - s;
#pragma unroll
    for (int i = 0; i < 10; ++i) {
        int idx = base + i;
        if (idx < N_NODES) {
            g_rowstart[idx] = run;
            g_cursor[idx] = run;
            run += c[i];
            g_count[idx] = 0;
        }
    }
    if (t == 1023) g_rowstart[N_NODES] = warpsum[31];
}

// ---------------- launch 3: CSR fill (1250) || h GEMM + agg zero (1250) || weight prep (33) ----------------
__global__ __launch_bounds__(256) void k_fill_plus(const int* __restrict__ recv,
                                                   const int* __restrict__ send,
                                                   const float* __restrict__ nf,
                                                   const float* __restrict__ Wup,
                                                   const float* __restrict__ W1,
                                                   const float* __restrict__ W2,
                                                   const float* __restrict__ W3,
                                                   const float* __restrict__ W4,
                                                   const float* __restrict__ Wd) {
    int t = threadIdx.x;
    int b = blockIdx.x;

    if (b < 1250) {
        // CSR fill
        int e = b * 256 + t;
        int r = recv[e];
        int pos = atomicAdd(&g_cursor[r], 1);
        g_csr[pos] = e;
        g_send[pos] = send[e];
        g_recv[pos] = r;
        return;
    }

    if (b >= 2500) {
        // weight prep: uint4 { tf32 W[k0][n0], W[k0+4][n0], W[k0][n1], W[k0+4][n1] }
        int u = (b - 2500) * 256 + t;
        if (u >= 8320) return;
        const float* src; int rs, co, KK, local;
        if (u < 128)       { src = W1; rs = 64;  co = 0;   KK = 1; local = u; }
        else if (u < 1152) { src = W2; rs = 64;  co = 0;   KK = 8; local = u - 128; }
        else if (u < 2176) { src = W3; rs = 64;  co = 0;   KK = 8; local = u - 1152; }
        else if (u < 3200) { src = W4; rs = 192; co = 0;   KK = 8; local = u - 2176; }
        else if (u < 4224) { src = W4; rs = 192; co = 64;  KK = 8; local = u - 3200; }
        else if (u < 5248) { src = W4; rs = 192; co = 128; KK = 8; local = u - 4224; }
        else               { int v = u - 5248; src = Wd + (v >> 10) * 4096;
                             rs = 64; co = 0; KK = 8; local = v & 1023; }
        int lane = local & 31; int rest = local >> 5;
        int np = rest & 1; rest >>= 1;
        int kk = rest % KK; int hb = rest / KK;
        int n0 = co + hb * 32 + np * 16 + (lane >> 2);
        int n1 = n0 + 8;
        int k0 = kk * 8 + (lane & 3);
        g_wfrag[u] = make_uint4(f2tf32(src[(size_t)k0 * rs + n0]),
                                f2tf32(src[(size_t)(k0 + 4) * rs + n0]),
                                f2tf32(src[(size_t)k0 * rs + n1]),
                                f2tf32(src[(size_t)(k0 + 4) * rs + n1]));
        return;
    }

    // h GEMM block (nodes [nb0, nb0+8)) + zero its g_agg slice
    int hb = b - 1250;
    {
        float4* aggb = (float4*)g_agg + (size_t)hb * 1152;
        for (int i = t; i < 1152; i += 256)
            aggb[i] = make_float4(0.f, 0.f, 0.f, 0.f);
    }
    __shared__ float sW[64 * 64];
    __shared__ float sN[8 * 64];
    for (int idx = t; idx < 1024; idx += 256)
        ((float4*)sW)[idx] = ((const float4*)Wup)[idx];
    int n0 = hb * 8;                          // 1250 * 8 = 10000
    if (t < 128)
        ((float4*)sN)[t] = ((const float4*)(nf + (size_t)n0 * 64))[t];
    __syncthreads();

#pragma unroll
    for (int j = 0; j < 2; ++j) {
        int o = t + j * 256;
        int row = o >> 6, c = o & 63;
        float a0 = 0.f, a1 = 0.f;
#pragma unroll
        for (int k = 0; k < 64; k += 2) {
            a0 = fmaf(sN[row * 64 + k],     sW[k * 64 + c],       a0);
            a1 = fmaf(sN[row * 64 + k + 1], sW[(k + 1) * 64 + c], a1);
        }
        g_h[(size_t)(n0 + row) * 64 + c] = (a0 + a1) * 0.125f;
    }
}

// ---------------- launch 4 (profiled): warp-autonomous fused MLP + SH + TP + scatter ----------------
// Each warp owns 16 CSR positions end-to-end; activations in registers between
// layers (C-frag -> A-frag shuffle conversion); weights streamed as uint4;
// epilogue flushes via vector v2 reductions (lane owns channels 2l, 2l+1).

__device__ __forceinline__ void layer64(int base, const uint32_t A0[8],
                                        const uint32_t A1[8], const uint32_t A2[8],
                                        const uint32_t A3[8], float acc[8][4],
                                        int lane) {
#pragma unroll
    for (int j = 0; j < 8; ++j) {
        acc[j][0] = 0.f; acc[j][1] = 0.f; acc[j][2] = 0.f; acc[j][3] = 0.f;
    }
#pragma unroll
    for (int kk = 0; kk < 8; ++kk) {
#pragma unroll
        for (int hb = 0; hb < 2; ++hb) {
#pragma unroll
            for (int np = 0; np < 2; ++np) {
                uint4 b = __ldg(&g_wfrag[base + (((hb * 8 + kk) * 2 + np) * 32) + lane]);
                int j = hb * 4 + np * 2;
                mma_tf32(acc[j],     A0[kk], A1[kk], A2[kk], A3[kk], b.x, b.y);
                mma_tf32(acc[j + 1], A0[kk], A1[kk], A2[kk], A3[kk], b.z, b.w);
            }
        }
    }
}

// C-frag -> next layer A-frag conversion (scale + silu + tf32), via shuffles.
__device__ __forceinline__ void cvt_frag(const float acc[8][4], float scale,
                                         uint32_t A0[8], uint32_t A1[8],
                                         uint32_t A2[8], uint32_t A3[8],
                                         int lane, int tid4) {
    int src  = (lane & 28) | (tid4 >> 1);
    int src2 = src + 2;
    bool odd = (tid4 & 1);
#pragma unroll
    for (int j = 0; j < 8; ++j) {
        uint32_t c0 = f2tf32(silu_f(acc[j][0] * scale));
        uint32_t c1 = f2tf32(silu_f(acc[j][1] * scale));
        uint32_t c2 = f2tf32(silu_f(acc[j][2] * scale));
        uint32_t c3 = f2tf32(silu_f(acc[j][3] * scale));
        uint32_t s0 = __shfl_sync(0xffffffffu, c0, src);
        uint32_t s1 = __shfl_sync(0xffffffffu, c1, src);
        uint32_t s2 = __shfl_sync(0xffffffffu, c2, src);
        uint32_t s3 = __shfl_sync(0xffffffffu, c3, src);
        uint32_t u0 = __shfl_sync(0xffffffffu, c0, src2);
        uint32_t u1 = __shfl_sync(0xffffffffu, c1, src2);
        uint32_t u2 = __shfl_sync(0xffffffffu, c2, src2);
        uint32_t u3 = __shfl_sync(0xffffffffu, c3, src2);
        A0[j] = odd ? s1 : s0;
        A1[j] = odd ? s3 : s2;
        A2[j] = odd ? u1 : u0;
        A3[j] = odd ? u3 : u2;
    }
}

template <int D, int KOFF>
__device__ __forceinline__ void l4_chunk(int base, const uint32_t A0[8],
                                         const uint32_t A1[8], const uint32_t A2[8],
                                         const uint32_t A3[8],
                                         const float2 hf0[8], const float2 hf1[8],
                                         float* __restrict__ wMsg,
                                         const float* __restrict__ wSh,
                                         const int* __restrict__ wRecv,
                                         int lane, int gid, int tid4) {
    float acc[8][4];
    layer64(base, A0, A1, A2, A3, acc, lane);

    const float S = 1.f / 256.f;   // 1/sqrt(64) / avg_neigh
#pragma unroll
    for (int j = 0; j < 8; ++j) {
        int col = j * 8 + 2 * tid4;
        *(float2*)(wMsg + gid * 66 + col) =
            make_float2(acc[j][0] * hf0[j].x * S, acc[j][1] * hf0[j].y * S);
        *(float2*)(wMsg + (gid + 8) * 66 + col) =
            make_float2(acc[j][2] * hf1[j].x * S, acc[j][3] * hf1[j].y * S);
    }
    __syncwarp();

    // warp-local segment reduction: lane owns channels (2*lane, 2*lane+1)
    {
        int ncur = wRecv[0];
        float a[D][2];
#pragma unroll
        for (int k = 0; k < D; ++k) { a[k][0] = 0.f; a[k][1] = 0.f; }
#pragma unroll 4
        for (int r = 0; r < 16; ++r) {
            int n = wRecv[r];
            if (n != ncur) {
#pragma unroll
                for (int k = 0; k < D; ++k) {
                    red2(&g_agg[(size_t)(ncur * 9 + KOFF + k) * 64 + 2 * lane],
                         a[k][0], a[k][1]);
                    a[k][0] = 0.f; a[k][1] = 0.f;
                }
                ncur = n;
            }
            float2 m = *(const float2*)(wMsg + r * 66 + 2 * lane);
#pragma unroll
            for (int k = 0; k < D; ++k) {
                float s = wSh[r * 12 + KOFF + k];
                a[k][0] = fmaf(m.x, s, a[k][0]);
                a[k][1] = fmaf(m.y, s, a[k][1]);
            }
        }
#pragma unroll
        for (int k = 0; k < D; ++k)
            red2(&g_agg[(size_t)(ncur * 9 + KOFF + k) * 64 + 2 * lane],
                 a[k][0], a[k][1]);
    }
    __syncwarp();
}

__global__ __launch_bounds__(256, 2) void k_edge(const float* __restrict__ evec,
                                                 const float* __restrict__ rad) {
    __shared__ __align__(16) float sMsgAll[8][16 * 66];   // 33792 B
    __shared__ __align__(16) float sShAll[8][16 * 12];    // 6144 B
    __shared__ int sMeta[8][32];                          // 1024 B

    int t = threadIdx.x, lane = t & 31, warp = t >> 5;
    int gid = lane >> 2, tid4 = lane & 3;
    float* wMsg = sMsgAll[warp];
    float* wSh  = sShAll[warp];
    int* wRecv  = sMeta[warp];
    int* wSend  = sMeta[warp] + 16;
    int pos0 = blockIdx.x * 128 + warp * 16;

    // init: lanes 0..15 handle one row each (SH + meta)
    if (lane < 16) {
        int pos = pos0 + lane;
        int e = g_csr[pos];
        wRecv[lane] = g_recv[pos];
        wSend[lane] = g_send[pos];
        float x = evec[(size_t)e * 3], y = evec[(size_t)e * 3 + 1],
              z = evec[(size_t)e * 3 + 2];
        float rn = rsqrtf(x * x + y * y + z * z);
        x *= rn; y *= rn; z *= rn;
        const float c3  = 1.7320508075688772f;
        const float c15 = 3.872983346207417f;
        const float c5h = 1.118033988749895f;
        const float c15h= 1.9364916731037085f;
        float* o = wSh + lane * 12;
        o[0] = 1.f;
        o[1] = c3 * x; o[2] = c3 * y; o[3] = c3 * z;
        o[4] = c15 * x * y; o[5] = c15 * y * z;
        o[6] = c5h * (3.f * z * z - 1.f);
        o[7] = c15 * x * z; o[8] = c15h * (x * x - y * y);
    }
    __syncwarp();

    // L1 A-fragments straight from rad (rows gid, gid+8; cols tid4, tid4+4)
    int e0 = g_csr[pos0 + gid], e1 = g_csr[pos0 + gid + 8];
    uint32_t r0 = f2tf32(__ldg(rad + (size_t)e0 * 8 + tid4));
    uint32_t r1 = f2tf32(__ldg(rad + (size_t)e1 * 8 + tid4));
    uint32_t r2 = f2tf32(__ldg(rad + (size_t)e0 * 8 + tid4 + 4));
    uint32_t r3 = f2tf32(__ldg(rad + (size_t)e1 * 8 + tid4 + 4));

    float acc[8][4];
    uint32_t A0[8], A1[8], A2[8], A3[8];

    // L1: [16,8]@[8,64] — 4 uint4 weight loads
#pragma unroll
    for (int j = 0; j < 8; ++j) {
        acc[j][0] = 0.f; acc[j][1] = 0.f; acc[j][2] = 0.f; acc[j][3] = 0.f;
    }
#pragma unroll
    for (int hb = 0; hb < 2; ++hb)
#pragma unroll
        for (int np = 0; np < 2; ++np) {
            uint4 b = __ldg(&g_wfrag[U_W1 + ((hb * 2 + np) * 32) + lane]);
            int j = hb * 4 + np * 2;
            mma_tf32(acc[j],     r0, r1, r2, r3, b.x, b.y);
            mma_tf32(acc[j + 1], r0, r1, r2, r3, b.z, b.w);
        }
    cvt_frag(acc, 0.35355339059327373f, A0, A1, A2, A3, lane, tid4);

    // L2
    layer64(U_W2, A0, A1, A2, A3, acc, lane);
    cvt_frag(acc, 0.125f, A0, A1, A2, A3, lane, tid4);

    // L3
    layer64(U_W3, A0, A1, A2, A3, acc, lane);
    cvt_frag(acc, 0.125f, A0, A1, A2, A3, lane, tid4);

    // h fragments (register-resident across all 3 chunks)
    int s0r = wSend[gid], s1r = wSend[gid + 8];
    float2 hf0[8], hf1[8];
#pragma unroll
    for (int j = 0; j < 8; ++j) {
        hf0[j] = *(const float2*)(g_h + (size_t)s0r * 64 + j * 8 + 2 * tid4);
        hf1[j] = *(const float2*)(g_h + (size_t)s1r * 64 + j * 8 + 2 * tid4);
    }

    // L4 chunks + tensor product + warp-local segment scatter
    l4_chunk<1, 0>(U_W4 + 0 * 1024, A0, A1, A2, A3, hf0, hf1,
                   wMsg, wSh, wRecv, lane, gid, tid4);
    l4_chunk<3, 1>(U_W4 + 1 * 1024, A0, A1, A2, A3, hf0, hf1,
                   wMsg, wSh, wRecv, lane, gid, tid4);
    l4_chunk<5, 4>(U_W4 + 2 * 1024, A0, A1, A2, A3, hf0, hf1,
                   wMsg, wSh, wRecv, lane, gid, tid4);
}

// ---------------- launch 5: linear_down as warp-autonomous tf32 MMA ----------------
// Row space per l: (node, m) pairs: l=0 -> 10000 rows, l=1 -> 30000, l=2 -> 50000.
// 16-row tiles: 625 + 1875 + 3125 = 5625 warps. No smem, no barriers, no atomics.
template <int D, int KOFF, int OFF>
__device__ __forceinline__ void down_tile(int tile, int wbase, float* __restrict__ out,
                                          int lane, int gid, int tid4) {
    int R0 = tile * 16 + gid, R1 = R0 + 8;
    int n0, m0, n1, m1;
    if (D == 1) { n0 = R0; m0 = 0; n1 = R1; m1 = 0; }
    else {
        n0 = R0 / D; m0 = R0 - n0 * D;
        n1 = R1 / D; m1 = R1 - n1 * D;
    }
    const float* p0 = g_agg + (size_t)n0 * 576 + (KOFF + m0) * 64;
    const float* p1 = g_agg + (size_t)n1 * 576 + (KOFF + m1) * 64;

    float acc[8][4];
#pragma unroll
    for (int j = 0; j < 8; ++j) {
        acc[j][0] = 0.f; acc[j][1] = 0.f; acc[j][2] = 0.f; acc[j][3] = 0.f;
    }
#pragma unroll
    for (int kk = 0; kk < 8; ++kk) {
        int c0 = kk * 8 + tid4;
        uint32_t a0 = f2tf32(__ldg(p0 + c0));
        uint32_t a1 = f2tf32(__ldg(p1 + c0));
        uint32_t a2 = f2tf32(__ldg(p0 + c0 + 4));
        uint32_t a3 = f2tf32(__ldg(p1 + c0 + 4));
#pragma unroll
        for (int hb = 0; hb < 2; ++hb)
#pragma unroll
            for (int np = 0; np < 2; ++np) {
                uint4 b = __ldg(&g_wfrag[wbase + (((hb * 8 + kk) * 2 + np) * 32) + lane]);
                int j = hb * 4 + np * 2;
                mma_tf32(acc[j],     a0, a1, a2, a3, b.x, b.y);
                mma_tf32(acc[j + 1], a0, a1, a2, a3, b.z, b.w);
            }
    }

    float* o0 = out + (size_t)n0 * 576 + OFF + m0;
    float* o1 = out + (size_t)n1 * 576 + OFF + m1;
#pragma unroll
    for (int j = 0; j < 8; ++j) {
        int dch = j * 8 + 2 * tid4;
        o0[dch * D]       = acc[j][0] * 0.125f;
        o0[(dch + 1) * D] = acc[j][1] * 0.125f;
        o1[dch * D]       = acc[j][2] * 0.125f;
        o1[(dch + 1) * D] = acc[j][3] * 0.125f;
    }
}

__global__ __launch_bounds__(256) void k_down(float* __restrict__ out) {
    int t = threadIdx.x, lane = t & 31, warp = t >> 5;
    int gid = lane >> 2, tid4 = lane & 3;
    int W = blockIdx.x * 8 + warp;
    if (W < 625)
        down_tile<1, 0, 0>(W, U_WD, out, lane, gid, tid4);
    else if (W < 2500)
        down_tile<3, 1, 64>(W - 625, U_WD + 1024, out, lane, gid, tid4);
    else if (W < 5625)
        down_tile<5, 4, 256>(W - 2500, U_WD + 2048, out, lane, gid, tid4);
}

// ---------------- launch ----------------
extern "C" void kernel_launch(void* const* d_in, const int* in_sizes, int n_in,
                              void* d_out, int out_size) {
    const float* evec = (const float*)d_in[0];
    const float* nf   = (const float*)d_in[1];
    const float* rad  = (const float*)d_in[2];
    const int* senders   = (const int*)d_in[3];
    const int* receivers = (const int*)d_in[4];
    const float* Wup = (const float*)d_in[5];
    const float* W1  = (const float*)d_in[6];
    const float* W2  = (const float*)d_in[7];
    const float* W3  = (const float*)d_in[8];
    const float* W4  = (const float*)d_in[9];
    const float* Wd  = (const float*)d_in[10];
    float* out = (float*)d_out;

    k_hist<<<N_EDGES / 256, 256>>>(receivers);
    k_scan<<<1, 1024>>>();
    k_fill_plus<<<2533, 256>>>(receivers, senders, nf, Wup, W1, W2, W3, W4, Wd);
    k_edge<<<N_EDGES / 128, 256>>>(evec, rad);
    k_down<<<704, 256>>>(out);
}

// round 14
// speedup vs baseline: 1.9865x; 1.3223x over previous
#include <cuda_runtime.h>
#include <cstdint>

#define N_NODES 10000
#define N_EDGES 320000

// ---------------- scratch (device globals; allocation-free) ----------------
__device__ float g_h[N_NODES * 64];                 // 2.56 MB
__device__ float g_agg[(size_t)N_NODES * 576];      // 23 MB; zeroed by k_fill_plus each call
__device__ int   g_count[N_NODES];                  // zeroed by k_scan after read
__device__ int   g_rowstart[N_NODES + 1];
__device__ int   g_cursor[N_NODES];
__device__ int   g_csr[N_EDGES];
__device__ int   g_send[N_EDGES];
__device__ int   g_recv[N_EDGES];
__device__ uint4 g_wfrag[4224];                     // fragment-ordered fp16 weights (67.6KB)

// uint4 offsets into g_wfrag (fp16 m16n8k16 fragments)
#define U_W1 0          // 128
#define U_W2 128        // 512
#define U_W3 640        // 512
#define U_W4 1152       // + chunk*512 (3 chunks)
#define U_WD 2688       // + l*512 (3 l's)

__device__ __forceinline__ float silu_f(float x) {
    return __fdividef(x, 1.f + __expf(-x));
}

// pack two f32 -> f16x2 {lo, hi}
__device__ __forceinline__ uint32_t f22h2(float lo, float hi) {
    uint32_t r;
    asm("cvt.rn.f16x2.f32 %0, %1, %2;" : "=r"(r) : "f"(hi), "f"(lo));
    return r;
}

__device__ __forceinline__ void mma_f16(float acc[4], uint32_t a0, uint32_t a1,
                                        uint32_t a2, uint32_t a3,
                                        uint32_t b0, uint32_t b1) {
    asm volatile(
        "mma.sync.aligned.m16n8k16.row.col.f32.f16.f16.f32 "
        "{%0,%1,%2,%3}, {%4,%5,%6,%7}, {%8,%9}, {%0,%1,%2,%3};\n"
        : "+f"(acc[0]), "+f"(acc[1]), "+f"(acc[2]), "+f"(acc[3])
        : "r"(a0), "r"(a1), "r"(a2), "r"(a3), "r"(b0), "r"(b1));
}

// fire-and-forget vector float2 reduction (sm_90+)
__device__ __forceinline__ void red2(float* p, float x, float y) {
    asm volatile("red.global.add.v2.f32 [%0], {%1, %2};"
                 :: "l"(p), "f"(x), "f"(y) : "memory");
}

// ---------------- launch 1: edge count histogram ONLY ----------------
__global__ __launch_bounds__(256) void k_hist(const int* __restrict__ recv) {
    int e = blockIdx.x * 256 + threadIdx.x;
    atomicAdd(&g_count[recv[e]], 1);          // N_EDGES % 256 == 0
}

// ---------------- launch 2: parallel exclusive scan (+ zero g_count) ----------------
__global__ __launch_bounds__(1024) void k_scan() {
    __shared__ int warpsum[32];
    int t = threadIdx.x, lane = t & 31, w = t >> 5;
    int base = t * 10;
    int c[10];
    int s = 0;
#pragma unroll
    for (int i = 0; i < 10; ++i) {
        int idx = base + i;
        c[i] = (idx < N_NODES) ? g_count[idx] : 0;
        s += c[i];
    }
    int pre = s;
#pragma unroll
    for (int d = 1; d < 32; d <<= 1) {
        int v = __shfl_up_sync(0xffffffffu, pre, d);
        if (lane >= d) pre += v;
    }
    if (lane == 31) warpsum[w] = pre;
    __syncthreads();
    if (w == 0) {
        int v = warpsum[lane];
#pragma unroll
        for (int d = 1; d < 32; d <<= 1) {
            int u = __shfl_up_sync(0xffffffffu, v, d);
            if (lane >= d) v += u;
        }
        warpsum[lane] = v;
    }
    __syncthreads();
    int wbase = (w > 0) ? warpsum[w - 1] : 0;
    int run = wbase + pre - s;
#pragma unroll
    for (int i = 0; i < 10; ++i) {
        int idx = base + i;
        if (idx < N_NODES) {
            g_rowstart[idx] = run;
            g_cursor[idx] = run;
            run += c[i];
            g_count[idx] = 0;
        }
    }
    if (t == 1023) g_rowstart[N_NODES] = warpsum[31];
}

// ---------------- launch 3: CSR fill (1250) || h GEMM + agg zero (1250) || weight prep (17) ----------------
__global__ __launch_bounds__(256) void k_fill_plus(const int* __restrict__ recv,
                                                   const int* __restrict__ send,
                                                   const float* __restrict__ nf,
                                                   const float* __restrict__ Wup,
                                                   const float* __restrict__ W1,
                                                   const float* __restrict__ W2,
                                                   const float* __restrict__ W3,
                                                   const float* __restrict__ W4,
                                                   const float* __restrict__ Wd) {
    int t = threadIdx.x;
    int b = blockIdx.x;

    if (b < 1250) {
        // CSR fill
        int e = b * 256 + t;
        int r = recv[e];
        int pos = atomicAdd(&g_cursor[r], 1);
        g_csr[pos] = e;
        g_send[pos] = send[e];
        g_recv[pos] = r;
        return;
    }

    if (b >= 2500) {
        // fp16 weight prep: uint4 = { b0(n0), b1(n0), b0(n1), b1(n1) }
        // b0 = {W[k0][n] lo, W[k0+1][n] hi}, b1 = {W[k0+8][n], W[k0+9][n]},
        // n0 = co + jp*16 + gid, n1 = n0+8, k0 = kk*16 + 2*tid4.
        int u = (b - 2500) * 256 + t;
        if (u >= 4224) return;
        const float* src; int rs, co, KK, kmax, local;
        if (u < 128)        { src = W1; rs = 64;  co = 0;   KK = 1; kmax = 8;  local = u; }
        else if (u < 640)   { src = W2; rs = 64;  co = 0;   KK = 4; kmax = 64; local = u - 128; }
        else if (u < 1152)  { src = W3; rs = 64;  co = 0;   KK = 4; kmax = 64; local = u - 640; }
        else if (u < 1664)  { src = W4; rs = 192; co = 0;   KK = 4; kmax = 64; local = u - 1152; }
        else if (u < 2176)  { src = W4; rs = 192; co = 64;  KK = 4; kmax = 64; local = u - 1664; }
        else if (u < 2688)  { src = W4; rs = 192; co = 128; KK = 4; kmax = 64; local = u - 2176; }
        else { int v = u - 2688; src = Wd + (v / 512) * 4096;
               rs = 64; co = 0; KK = 4; kmax = 64; local = v & 511; }
        int lane = local & 31, rest = local >> 5;
        int kk = rest % KK, jp = rest / KK;
        int gid = lane >> 2, tid4 = lane & 3;
        int n0 = co + jp * 16 + gid, n1 = n0 + 8;
        int k0 = kk * 16 + 2 * tid4;
        uint32_t x = f22h2(src[(size_t)k0 * rs + n0], src[(size_t)(k0 + 1) * rs + n0]);
        uint32_t z = f22h2(src[(size_t)k0 * rs + n1], src[(size_t)(k0 + 1) * rs + n1]);
        uint32_t y = 0, w = 0;
        if (k0 + 8 < kmax) {
            y = f22h2(src[(size_t)(k0 + 8) * rs + n0], src[(size_t)(k0 + 9) * rs + n0]);
            w = f22h2(src[(size_t)(k0 + 8) * rs + n1], src[(size_t)(k0 + 9) * rs + n1]);
        }
        g_wfrag[u] = make_uint4(x, y, z, w);
        return;
    }

    // h GEMM block (nodes [hb*8, hb*8+8)) + zero its g_agg slice
    int hb = b - 1250;
    {
        float4* aggb = (float4*)g_agg + (size_t)hb * 1152;
        for (int i = t; i < 1152; i += 256)
            aggb[i] = make_float4(0.f, 0.f, 0.f, 0.f);
    }
    __shared__ float sW[64 * 64];
    __shared__ float sN[8 * 64];
    for (int idx = t; idx < 1024; idx += 256)
        ((float4*)sW)[idx] = ((const float4*)Wup)[idx];
    int n0 = hb * 8;                          // 1250 * 8 = 10000
    if (t < 128)
        ((float4*)sN)[t] = ((const float4*)(nf + (size_t)n0 * 64))[t];
    __syncthreads();

#pragma unroll
    for (int j = 0; j < 2; ++j) {
        int o = t + j * 256;
        int row = o >> 6, c = o & 63;
        float a0 = 0.f, a1 = 0.f;
#pragma unroll
        for (int k = 0; k < 64; k += 2) {
            a0 = fmaf(sN[row * 64 + k],     sW[k * 64 + c],       a0);
            a1 = fmaf(sN[row * 64 + k + 1], sW[(k + 1) * 64 + c], a1);
        }
        g_h[(size_t)(n0 + row) * 64 + c] = (a0 + a1) * 0.125f;
    }
}

// ---------------- launch 4 (profiled): warp-autonomous fused MLP + SH + TP + scatter ----------------
// fp16 m16n8k16 datapath: K=16 per mma, B-fragments streamed as uint4 (2 n-tiles),
// layer-to-layer conversion is pure per-lane cvt (no shuffles).

template <int KK>
__device__ __forceinline__ void layer_f16(int base, const uint32_t A0[4],
                                          const uint32_t A1[4], const uint32_t A2[4],
                                          const uint32_t A3[4], float acc[8][4],
                                          int lane) {
#pragma unroll
    for (int j = 0; j < 8; ++j) {
        acc[j][0] = 0.f; acc[j][1] = 0.f; acc[j][2] = 0.f; acc[j][3] = 0.f;
    }
#pragma unroll
    for (int kk = 0; kk < KK; ++kk) {
#pragma unroll
        for (int jp = 0; jp < 4; ++jp) {
            uint4 b = __ldg(&g_wfrag[base + ((jp * KK + kk) * 32) + lane]);
            mma_f16(acc[2 * jp],     A0[kk], A1[kk], A2[kk], A3[kk], b.x, b.y);
            mma_f16(acc[2 * jp + 1], A0[kk], A1[kk], A2[kk], A3[kk], b.z, b.w);
        }
    }
}

// C-frags -> next layer A-frags: scale + silu + f16 pack, all lane-local.
__device__ __forceinline__ void cvt_f16(const float acc[8][4], float scale,
                                        uint32_t A0[4], uint32_t A1[4],
                                        uint32_t A2[4], uint32_t A3[4]) {
#pragma unroll
    for (int kk = 0; kk < 4; ++kk) {
        A0[kk] = f22h2(silu_f(acc[2 * kk][0] * scale),     silu_f(acc[2 * kk][1] * scale));
        A1[kk] = f22h2(silu_f(acc[2 * kk][2] * scale),     silu_f(acc[2 * kk][3] * scale));
        A2[kk] = f22h2(silu_f(acc[2 * kk + 1][0] * scale), silu_f(acc[2 * kk + 1][1] * scale));
        A3[kk] = f22h2(silu_f(acc[2 * kk + 1][2] * scale), silu_f(acc[2 * kk + 1][3] * scale));
    }
}

template <int D, int KOFF>
__device__ __forceinline__ void l4_chunk(int base, const uint32_t A0[4],
                                         const uint32_t A1[4], const uint32_t A2[4],
                                         const uint32_t A3[4],
                                         const float2 hf0[8], const float2 hf1[8],
                                         float* __restrict__ wMsg,
                                         const float* __restrict__ wSh,
                                         const int* __restrict__ wRecv,
                                         int lane, int gid, int tid4) {
    float acc[8][4];
    layer_f16<4>(base, A0, A1, A2, A3, acc, lane);

    const float S = 1.f / 256.f;   // 1/sqrt(64) / avg_neigh
#pragma unroll
    for (int j = 0; j < 8; ++j) {
        int col = j * 8 + 2 * tid4;
        *(float2*)(wMsg + gid * 66 + col) =
            make_float2(acc[j][0] * hf0[j].x * S, acc[j][1] * hf0[j].y * S);
        *(float2*)(wMsg + (gid + 8) * 66 + col) =
            make_float2(acc[j][2] * hf1[j].x * S, acc[j][3] * hf1[j].y * S);
    }
    __syncwarp();

    // warp-local segment reduction: lane owns channels (2*lane, 2*lane+1)
    {
        int ncur = wRecv[0];
        float a[D][2];
#pragma unroll
        for (int k = 0; k < D; ++k) { a[k][0] = 0.f; a[k][1] = 0.f; }
#pragma unroll 4
        for (int r = 0; r < 16; ++r) {
            int n = wRecv[r];
            if (n != ncur) {
#pragma unroll
                for (int k = 0; k < D; ++k) {
                    red2(&g_agg[(size_t)(ncur * 9 + KOFF + k) * 64 + 2 * lane],
                         a[k][0], a[k][1]);
                    a[k][0] = 0.f; a[k][1] = 0.f;
                }
                ncur = n;
            }
            float2 m = *(const float2*)(wMsg + r * 66 + 2 * lane);
#pragma unroll
            for (int k = 0; k < D; ++k) {
                float s = wSh[r * 12 + KOFF + k];
                a[k][0] = fmaf(m.x, s, a[k][0]);
                a[k][1] = fmaf(m.y, s, a[k][1]);
            }
        }
#pragma unroll
        for (int k = 0; k < D; ++k)
            red2(&g_agg[(size_t)(ncur * 9 + KOFF + k) * 64 + 2 * lane],
                 a[k][0], a[k][1]);
    }
    __syncwarp();
}

__global__ __launch_bounds__(256, 2) void k_edge(const float* __restrict__ evec,
                                                 const float* __restrict__ rad) {
    __shared__ __align__(16) float sMsgAll[8][16 * 66];   // 33792 B
    __shared__ __align__(16) float sShAll[8][16 * 12];    // 6144 B
    __shared__ int sMeta[8][32];                          // 1024 B

    int t = threadIdx.x, lane = t & 31, warp = t >> 5;
    int gid = lane >> 2, tid4 = lane & 3;
    float* wMsg = sMsgAll[warp];
    float* wSh  = sShAll[warp];
    int* wRecv  = sMeta[warp];
    int* wSend  = sMeta[warp] + 16;
    int pos0 = blockIdx.x * 128 + warp * 16;

    // init: lanes 0..15 handle one row each (SH + meta)
    if (lane < 16) {
        int pos = pos0 + lane;
        int e = g_csr[pos];
        wRecv[lane] = g_recv[pos];
        wSend[lane] = g_send[pos];
        float x = evec[(size_t)e * 3], y = evec[(size_t)e * 3 + 1],
              z = evec[(size_t)e * 3 + 2];
        float rn = rsqrtf(x * x + y * y + z * z);
        x *= rn; y *= rn; z *= rn;
        const float c3  = 1.7320508075688772f;
        const float c15 = 3.872983346207417f;
        const float c5h = 1.118033988749895f;
        const float c15h= 1.9364916731037085f;
        float* o = wSh + lane * 12;
        o[0] = 1.f;
        o[1] = c3 * x; o[2] = c3 * y; o[3] = c3 * z;
        o[4] = c15 * x * y; o[5] = c15 * y * z;
        o[6] = c5h * (3.f * z * z - 1.f);
        o[7] = c15 * x * z; o[8] = c15h * (x * x - y * y);
    }
    __syncwarp();

    // L1 A-fragments straight from rad (rows gid, gid+8; k-cols 2*tid4, +1; high-k = 0)
    int e0 = g_csr[pos0 + gid], e1 = g_csr[pos0 + gid + 8];
    float2 ra0 = *(const float2*)(rad + (size_t)e0 * 8 + 2 * tid4);
    float2 ra1 = *(const float2*)(rad + (size_t)e1 * 8 + 2 * tid4);

    float acc[8][4];
    uint32_t A0[4], A1[4], A2[4], A3[4];
    A0[0] = f22h2(ra0.x, ra0.y);
    A1[0] = f22h2(ra1.x, ra1.y);
    A2[0] = 0u;
    A3[0] = 0u;

    // L1: [16,8]@[8,64]
    layer_f16<1>(U_W1, A0, A1, A2, A3, acc, lane);
    cvt_f16(acc, 0.35355339059327373f, A0, A1, A2, A3);

    // L2
    layer_f16<4>(U_W2, A0, A1, A2, A3, acc, lane);
    cvt_f16(acc, 0.125f, A0, A1, A2, A3);

    // L3
    layer_f16<4>(U_W3, A0, A1, A2, A3, acc, lane);
    cvt_f16(acc, 0.125f, A0, A1, A2, A3);

    // h fragments (register-resident across all 3 chunks)
    int s0r = wSend[gid], s1r = wSend[gid + 8];
    float2 hf0[8], hf1[8];
#pragma unroll
    for (int j = 0; j < 8; ++j) {
        hf0[j] = *(const float2*)(g_h + (size_t)s0r * 64 + j * 8 + 2 * tid4);
        hf1[j] = *(const float2*)(g_h + (size_t)s1r * 64 + j * 8 + 2 * tid4);
    }

    // L4 chunks + tensor product + warp-local segment scatter
    l4_chunk<1, 0>(U_W4 + 0 * 512, A0, A1, A2, A3, hf0, hf1,
                   wMsg, wSh, wRecv, lane, gid, tid4);
    l4_chunk<3, 1>(U_W4 + 1 * 512, A0, A1, A2, A3, hf0, hf1,
                   wMsg, wSh, wRecv, lane, gid, tid4);
    l4_chunk<5, 4>(U_W4 + 2 * 512, A0, A1, A2, A3, hf0, hf1,
                   wMsg, wSh, wRecv, lane, gid, tid4);
}

// ---------------- launch 5: linear_down as warp-autonomous fp16 MMA ----------------
// Row space per l: l=0 -> 10000 rows, l=1 -> 30000, l=2 -> 50000. 5625 16-row tiles.
template <int D, int KOFF, int OFF>
__device__ __forceinline__ void down_tile(int tile, int wbase, float* __restrict__ out,
                                          int lane, int gid, int tid4) {
    int R0 = tile * 16 + gid, R1 = R0 + 8;
    int n0, m0, n1, m1;
    if (D == 1) { n0 = R0; m0 = 0; n1 = R1; m1 = 0; }
    else {
        n0 = R0 / D; m0 = R0 - n0 * D;
        n1 = R1 / D; m1 = R1 - n1 * D;
    }
    const float* p0 = g_agg + (size_t)n0 * 576 + (KOFF + m0) * 64;
    const float* p1 = g_agg + (size_t)n1 * 576 + (KOFF + m1) * 64;

    float acc[8][4];
#pragma unroll
    for (int j = 0; j < 8; ++j) {
        acc[j][0] = 0.f; acc[j][1] = 0.f; acc[j][2] = 0.f; acc[j][3] = 0.f;
    }
#pragma unroll
    for (int kk = 0; kk < 4; ++kk) {
        int c0 = kk * 16 + 2 * tid4;
        float2 v00 = *(const float2*)(p0 + c0);
        float2 v01 = *(const float2*)(p0 + c0 + 8);
        float2 v10 = *(const float2*)(p1 + c0);
        float2 v11 = *(const float2*)(p1 + c0 + 8);
        uint32_t a0 = f22h2(v00.x, v00.y);
        uint32_t a1 = f22h2(v10.x, v10.y);
        uint32_t a2 = f22h2(v01.x, v01.y);
        uint32_t a3 = f22h2(v11.x, v11.y);
#pragma unroll
        for (int jp = 0; jp < 4; ++jp) {
            uint4 b = __ldg(&g_wfrag[wbase + ((jp * 4 + kk) * 32) + lane]);
            mma_f16(acc[2 * jp],     a0, a1, a2, a3, b.x, b.y);
            mma_f16(acc[2 * jp + 1], a0, a1, a2, a3, b.z, b.w);
        }
    }

    float* o0 = out + (size_t)n0 * 576 + OFF + m0;
    float* o1 = out + (size_t)n1 * 576 + OFF + m1;
#pragma unroll
    for (int j = 0; j < 8; ++j) {
        int dch = j * 8 + 2 * tid4;
        o0[dch * D]       = acc[j][0] * 0.125f;
        o0[(dch + 1) * D] = acc[j][1] * 0.125f;
        o1[dch * D]       = acc[j][2] * 0.125f;
        o1[(dch + 1) * D] = acc[j][3] * 0.125f;
    }
}

__global__ __launch_bounds__(256) void k_down(float* __restrict__ out) {
    int t = threadIdx.x, lane = t & 31, warp = t >> 5;
    int gid = lane >> 2, tid4 = lane & 3;
    int W = blockIdx.x * 8 + warp;
    if (W < 625)
        down_tile<1, 0, 0>(W, U_WD, out, lane, gid, tid4);
    else if (W < 2500)
        down_tile<3, 1, 64>(W - 625, U_WD + 512, out, lane, gid, tid4);
    else if (W < 5625)
        down_tile<5, 4, 256>(W - 2500, U_WD + 1024, out, lane, gid, tid4);
}

// ---------------- launch ----------------
extern "C" void kernel_launch(void* const* d_in, const int* in_sizes, int n_in,
                              void* d_out, int out_size) {
    const float* evec = (const float*)d_in[0];
    const float* nf   = (const float*)d_in[1];
    const float* rad  = (const float*)d_in[2];
    const int* senders   = (const int*)d_in[3];
    const int* receivers = (const int*)d_in[4];
    const float* Wup = (const float*)d_in[5];
    const float* W1  = (const float*)d_in[6];
    const float* W2  = (const float*)d_in[7];
    const float* W3  = (const float*)d_in[8];
    const float* W4  = (const float*)d_in[9];
    const float* Wd  = (const float*)d_in[10];
    float* out = (float*)d_out;

    k_hist<<<N_EDGES / 256, 256>>>(receivers);
    k_scan<<<1, 1024>>>();
    k_fill_plus<<<2517, 256>>>(receivers, senders, nf, Wup, W1, W2, W3, W4, Wd);
    k_edge<<<N_EDGES / 128, 256>>>(evec, rad);
    k_down<<<704, 256>>>(out);
}